// round 4
// baseline (speedup 1.0000x reference)
#include <cuda_runtime.h>
#include <math.h>
#include <cfloat>

// ---------------------------------------------------------------------------
// VQGAN forward, fp32 with packed FFMA2 (fma.rn.f32x2), P=4 (32-reg acc),
// row-shared loads, duplicated {w,w} weights in smem (LDS.64 broadcast).
// ---------------------------------------------------------------------------

#define NB 2

__device__ float g_h1[(size_t)NB * 64 * 32 * 32 * 32];
__device__ float g_h2[(size_t)NB * 128 * 16 * 16 * 16];
__device__ float g_h3[(size_t)NB * 256 * 8 * 8 * 8];
__device__ float g_lat[(size_t)NB * 256 * 512];
__device__ float g_q[(size_t)NB * 256 * 512];
__device__ float g_d1[(size_t)NB * 256 * 16 * 16 * 16];
__device__ float g_d2[(size_t)NB * 128 * 32 * 32 * 32];
__device__ float g_d3[(size_t)NB * 64 * 64 * 64 * 64];

typedef unsigned long long u64;

__device__ __forceinline__ u64 pack2(float a, float b) {
    u64 r;
    asm("mov.b64 %0, {%1, %2};" : "=l"(r) : "f"(a), "f"(b));
    return r;
}
__device__ __forceinline__ void fma2(u64& d, u64 a, u64 b) {
    asm("fma.rn.f32x2 %0, %1, %2, %0;" : "+l"(d) : "l"(a), "l"(b));
}
__device__ __forceinline__ float2 unpack2(u64 v) {
    float2 r;
    asm("mov.b64 {%0, %1}, %2;" : "=f"(r.x), "=f"(r.y) : "l"(v));
    return r;
}

// ---------------------------------------------------------------------------
// conv3d k=4 s=2 p=1 + ReLU. Thread: TC couts x 4 consecutive x-outputs.
// Row-shared loads (10 values), FFMA2 with stride-2 packed input pairs.
// ---------------------------------------------------------------------------
template <int Cin, int Cout, int Dout, int TC>
__global__ void __launch_bounds__(128)
conv_s2_relu(const float* __restrict__ in, const float* __restrict__ w,
             const float* __restrict__ bias, float* __restrict__ out)
{
    constexpr int Din = 2 * Dout;
    constexpr int CI_CHUNK = (Cin < 8) ? Cin : 8;
    __shared__ float2 ws2[CI_CHUNK][TC][64];

    const int tid = threadIdx.x;
    const int coBase = blockIdx.y * TC;
    const int b = blockIdx.z;
    const int s0 = blockIdx.x * 512 + tid * 4;
    const int ox0 = s0 % Dout;
    const int oy = (s0 / Dout) % Dout;
    const int oz = s0 / (Dout * Dout);
    const int ixb = 2 * ox0 - 1;                 // base x of vals[]
    const bool xin = (ixb >= 0) && (ixb + 9 <= Din - 1);

    u64 acc[2][TC];
#pragma unroll
    for (int j = 0; j < 2; j++)
#pragma unroll
        for (int c = 0; c < TC; c++) acc[j][c] = 0ULL;

    const float* inB = in + (size_t)b * Cin * Din * Din * Din;

    for (int ci0 = 0; ci0 < Cin; ci0 += CI_CHUNK) {
        for (int i = tid; i < CI_CHUNK * TC * 64; i += 128) {
            int ci = i / (TC * 64);
            int rem = i % (TC * 64);
            int co = rem / 64;
            int tap = rem % 64;
            float wv = w[((size_t)(coBase + co) * Cin + (ci0 + ci)) * 64 + tap];
            ws2[ci][co][tap] = make_float2(wv, wv);
        }
        __syncthreads();

#pragma unroll 1
        for (int ci = 0; ci < CI_CHUNK; ci++) {
            const float* inC = inB + (size_t)(ci0 + ci) * Din * Din * Din;
            const u64* wsu = reinterpret_cast<const u64*>(&ws2[ci][0][0]);
#pragma unroll
            for (int kd = 0; kd < 4; kd++) {
                const int iz = 2 * oz + kd - 1;
                if ((unsigned)iz >= (unsigned)Din) continue;
#pragma unroll
                for (int kh = 0; kh < 4; kh++) {
                    const int iy = 2 * oy + kh - 1;
                    if ((unsigned)iy >= (unsigned)Din) continue;
                    const float* row = inC + (size_t)iz * Din * Din + (size_t)iy * Din + ixb;

                    float vals[10];
                    if (xin) {
#pragma unroll
                        for (int j = 0; j < 10; j++) vals[j] = row[j];
                    } else {
#pragma unroll
                        for (int j = 0; j < 10; j++) {
                            int ix = ixb + j;
                            vals[j] = ((unsigned)ix < (unsigned)Din) ? row[j] : 0.f;
                        }
                    }
#pragma unroll
                    for (int kw = 0; kw < 4; kw++) {
                        const u64 u0 = pack2(vals[kw], vals[kw + 2]);
                        const u64 u1 = pack2(vals[kw + 4], vals[kw + 6]);
                        const int tap = kd * 16 + kh * 4 + kw;
#pragma unroll
                        for (int c = 0; c < TC; c++) {
                            const u64 w2 = wsu[c * 64 + tap];
                            fma2(acc[0][c], u0, w2);
                            fma2(acc[1][c], u1, w2);
                        }
                    }
                }
            }
        }
        __syncthreads();
    }

#pragma unroll
    for (int c = 0; c < TC; c++) {
        float bv = bias[coBase + c];
        size_t base = (((size_t)b * Cout + coBase + c) * Dout + oz) * Dout * Dout
                      + (size_t)oy * Dout + ox0;
        float2 r0 = unpack2(acc[0][c]);
        float2 r1 = unpack2(acc[1][c]);
        out[base + 0] = fmaxf(r0.x + bv, 0.f);
        out[base + 1] = fmaxf(r0.y + bv, 0.f);
        out[base + 2] = fmaxf(r1.x + bv, 0.f);
        out[base + 3] = fmaxf(r1.y + bv, 0.f);
    }
}

// ---------------------------------------------------------------------------
// 1x1 conv (enc4)
// ---------------------------------------------------------------------------
__global__ void conv1x1(const float* __restrict__ in, const float* __restrict__ w,
                        const float* __restrict__ bias, float* __restrict__ out)
{
    __shared__ float ws[8][256];
    const int tid = threadIdx.x;
    const int coBase = blockIdx.y * 8;
    const int b = blockIdx.z;
    const int s = blockIdx.x * 128 + tid;

    for (int i = tid; i < 8 * 256; i += 128)
        ws[i / 256][i % 256] = w[(size_t)(coBase + i / 256) * 256 + (i % 256)];
    __syncthreads();

    float acc[8];
#pragma unroll
    for (int c = 0; c < 8; c++) acc[c] = 0.f;

    const float* inB = in + (size_t)b * 256 * 512 + s;
    for (int ci = 0; ci < 256; ci++) {
        float v = inB[(size_t)ci * 512];
#pragma unroll
        for (int c = 0; c < 8; c++) acc[c] += v * ws[c][ci];
    }
#pragma unroll
    for (int c = 0; c < 8; c++)
        out[((size_t)b * 256 + coBase + c) * 512 + s] = acc[c] + bias[coBase + c];
}

// ---------------------------------------------------------------------------
// VQ (exact expand-norm formula, argmin tie -> smaller k)
// ---------------------------------------------------------------------------
__global__ void vq_kernel(const float* __restrict__ lat, const float* __restrict__ cb,
                          float* __restrict__ q, float* __restrict__ idx_out)
{
    __shared__ float4 latS[8][64];
    __shared__ float ln[8];
    __shared__ float bd[8][128];
    __shared__ int bk[8][128];
    __shared__ int wink[8];

    const int tid = threadIdx.x;
    const int vb = blockIdx.x * 8;

    for (int i = tid; i < 8 * 64; i += 128) {
        int v = i >> 6, d4 = i & 63;
        latS[v][d4] = ((const float4*)lat)[(size_t)(vb + v) * 64 + d4];
    }
    __syncthreads();

    if (tid < 8) {
        float s = 0.f;
        for (int d4 = 0; d4 < 64; d4++) {
            float4 l = latS[tid][d4];
            s += l.x * l.x + l.y * l.y + l.z * l.z + l.w * l.w;
        }
        ln[tid] = s;
    }
    __syncthreads();

    float best[8];
    int bestk[8];
#pragma unroll
    for (int v = 0; v < 8; v++) { best[v] = FLT_MAX; bestk[v] = 0; }

    for (int j = 0; j < 8; j++) {
        const int k = tid + j * 128;
        const float4* cbr = (const float4*)(cb + (size_t)k * 256);
        float dot[8];
        float cn = 0.f;
#pragma unroll
        for (int v = 0; v < 8; v++) dot[v] = 0.f;
        for (int d4 = 0; d4 < 64; d4++) {
            float4 c = cbr[d4];
            cn += c.x * c.x + c.y * c.y + c.z * c.z + c.w * c.w;
#pragma unroll
            for (int v = 0; v < 8; v++) {
                float4 l = latS[v][d4];
                dot[v] += c.x * l.x + c.y * l.y + c.z * l.z + c.w * l.w;
            }
        }
#pragma unroll
        for (int v = 0; v < 8; v++) {
            float d2 = ln[v] - 2.f * dot[v] + cn;
            if (d2 < best[v]) { best[v] = d2; bestk[v] = k; }
        }
    }

#pragma unroll
    for (int v = 0; v < 8; v++) { bd[v][tid] = best[v]; bk[v][tid] = bestk[v]; }
    __syncthreads();
    for (int s = 64; s > 0; s >>= 1) {
        if (tid < s) {
#pragma unroll
            for (int v = 0; v < 8; v++) {
                float dB = bd[v][tid + s];
                int kB = bk[v][tid + s];
                float dA = bd[v][tid];
                int kA = bk[v][tid];
                if (dB < dA || (dB == dA && kB < kA)) { bd[v][tid] = dB; bk[v][tid] = kB; }
            }
        }
        __syncthreads();
    }
    if (tid < 8) {
        wink[tid] = bk[tid][0];
        if (idx_out) idx_out[vb + tid] = (float)bk[tid][0];
    }
    __syncthreads();

    for (int i = tid; i < 8 * 256; i += 128) {
        int v = i >> 8, c = i & 255;
        int gn = vb + v;
        int b = gn >> 9, n = gn & 511;
        q[((size_t)b * 256 + c) * 512 + n] = cb[(size_t)wink[v] * 256 + c];
    }
}

// ---------------------------------------------------------------------------
// convtranspose3d k=4 s=2 p=1 + ReLU, 8 parity classes, 2x2x2 taps, FFMA2.
// P=4 outputs/thread; vals[6] row-shared; dup {w,w} weights in smem.
// ---------------------------------------------------------------------------
__device__ __forceinline__ int kparity(int r, int t) { return r ? (2 - 2 * t) : (1 + 2 * t); }

template <int Cin, int Cout, int Din, int TC>
__global__ void __launch_bounds__(128)
convT_relu(const float* __restrict__ in, const float* __restrict__ w,
           const float* __restrict__ bias, float* __restrict__ out)
{
    constexpr int Dout = 2 * Din;
    constexpr int CI_CHUNK = 16;
    __shared__ float2 ws2[CI_CHUNK][TC][8];

    const int tid = threadIdx.x;
    const int coBase = blockIdx.y * TC;
    const int bz = blockIdx.z;
    const int b = bz >> 3;
    const int cls = bz & 7;
    const int rz = (cls >> 2) & 1, ry = (cls >> 1) & 1, rx = cls & 1;

    const int zoff1 = rz ? 1 : -1;
    const int yoff1 = ry ? 1 : -1;
    const int xsh1 = rx ? 2 : 0;     // vals shift for tx=1 (tx=0 shift is 1)

    const int m0 = blockIdx.x * 512 + tid * 4;
    const int mx0 = m0 % Din;
    const int my = (m0 / Din) % Din;
    const int mz = m0 / (Din * Din);
    const bool xin = (mx0 >= 1) && (mx0 + 4 <= Din - 1);

    u64 acc[2][TC];
#pragma unroll
    for (int j = 0; j < 2; j++)
#pragma unroll
        for (int c = 0; c < TC; c++) acc[j][c] = 0ULL;

    const float* inB = in + (size_t)b * Cin * Din * Din * Din;

    for (int ci0 = 0; ci0 < Cin; ci0 += CI_CHUNK) {
        for (int i = tid; i < CI_CHUNK * TC * 8; i += 128) {
            int ci = i / (TC * 8);
            int rem = i % (TC * 8);
            int co = rem / 8;
            int t = rem % 8;
            int tz = (t >> 2) & 1, ty = (t >> 1) & 1, tx = t & 1;
            int tap = kparity(rz, tz) * 16 + kparity(ry, ty) * 4 + kparity(rx, tx);
            float wv = w[((size_t)(ci0 + ci) * Cout + coBase + co) * 64 + tap];
            ws2[ci][co][t] = make_float2(wv, wv);
        }
        __syncthreads();

#pragma unroll 1
        for (int ci = 0; ci < CI_CHUNK; ci++) {
            const float* inC = inB + (size_t)(ci0 + ci) * Din * Din * Din;
            const u64* wsu = reinterpret_cast<const u64*>(&ws2[ci][0][0]);
#pragma unroll
            for (int tz = 0; tz < 2; tz++) {
                const int iz = mz + (tz ? zoff1 : 0);
                if ((unsigned)iz >= (unsigned)Din) continue;
#pragma unroll
                for (int ty = 0; ty < 2; ty++) {
                    const int iy = my + (ty ? yoff1 : 0);
                    if ((unsigned)iy >= (unsigned)Din) continue;
                    const float* row = inC + (size_t)iz * Din * Din + (size_t)iy * Din + mx0 - 1;

                    float vals[6];
                    if (xin) {
#pragma unroll
                        for (int j = 0; j < 6; j++) vals[j] = row[j];
                    } else {
#pragma unroll
                        for (int j = 0; j < 6; j++) {
                            int ix = mx0 - 1 + j;
                            vals[j] = ((unsigned)ix < (unsigned)Din) ? row[j] : 0.f;
                        }
                    }
                    // packed operands: tx=0 -> shift 1; tx=1 -> shift xsh1
                    const u64 b0 = pack2(vals[1], vals[2]);
                    const u64 b1 = pack2(vals[3], vals[4]);
                    const u64 a0 = pack2(vals[xsh1], vals[xsh1 + 1]);
                    const u64 a1 = pack2(vals[xsh1 + 2], vals[xsh1 + 3]);

                    const int tb = tz * 4 + ty * 2;
#pragma unroll
                    for (int c = 0; c < TC; c++) {
                        const u64 w0 = wsu[c * 8 + tb];
                        fma2(acc[0][c], b0, w0);
                        fma2(acc[1][c], b1, w0);
                        const u64 w1 = wsu[c * 8 + tb + 1];
                        fma2(acc[0][c], a0, w1);
                        fma2(acc[1][c], a1, w1);
                    }
                }
            }
        }
        __syncthreads();
    }

    const int oz = 2 * mz + rz;
    const int oy = 2 * my + ry;
#pragma unroll
    for (int c = 0; c < TC; c++) {
        float bv = bias[coBase + c];
        size_t base = (((size_t)b * Cout + coBase + c) * Dout + oz) * Dout * Dout
                      + (size_t)oy * Dout + rx;
        float2 r0 = unpack2(acc[0][c]);
        float2 r1 = unpack2(acc[1][c]);
        out[base + 2 * (mx0 + 0)] = fmaxf(r0.x + bv, 0.f);
        out[base + 2 * (mx0 + 1)] = fmaxf(r0.y + bv, 0.f);
        out[base + 2 * (mx0 + 2)] = fmaxf(r1.x + bv, 0.f);
        out[base + 2 * (mx0 + 3)] = fmaxf(r1.y + bv, 0.f);
    }
}

// ---------------------------------------------------------------------------
// dec4: conv3d k=4 s=1 p=0, 64->3, + tanh. FFMA2, 8 x-outputs/thread.
// ---------------------------------------------------------------------------
__global__ void __launch_bounds__(128)
conv_final_tanh(const float* __restrict__ in, const float* __restrict__ w,
                const float* __restrict__ bias, float* __restrict__ out)
{
    __shared__ float ws[3 * 64 * 64];   // 48KB
    const int tid = threadIdx.x;
    for (int i = tid; i < 3 * 64 * 64; i += 128) ws[i] = w[i];
    __syncthreads();

    const int b = blockIdx.z;
    const int z = blockIdx.y;               // 0..60
    const int ry = tid / 8;                 // 0..15
    const int y = blockIdx.x * 16 + ry;     // 0..63
    const int x0 = (tid % 8) * 8;           // 0..56
    if (y >= 61) return;

    u64 acc[3][4];
#pragma unroll
    for (int c = 0; c < 3; c++)
#pragma unroll
        for (int j = 0; j < 4; j++) acc[c][j] = 0ULL;

    const float* inB = in + (size_t)b * 64 * 64 * 64 * 64;
#pragma unroll 1
    for (int ci = 0; ci < 64; ci++) {
        const float* inC = inB + (size_t)ci * 262144;
#pragma unroll
        for (int kd = 0; kd < 4; kd++) {
            const float* pz = inC + (size_t)(z + kd) * 4096;
#pragma unroll
            for (int kh = 0; kh < 4; kh++) {
                const float* row = pz + (size_t)(y + kh) * 64;
                float v[11];
#pragma unroll
                for (int jj = 0; jj < 11; jj++) {
                    int ix = x0 + jj;
                    v[jj] = (ix < 64) ? row[ix] : 0.f;
                }
#pragma unroll
                for (int kw = 0; kw < 4; kw++) {
                    u64 v2[4];
#pragma unroll
                    for (int j = 0; j < 4; j++) v2[j] = pack2(v[kw + 2 * j], v[kw + 2 * j + 1]);
#pragma unroll
                    for (int c = 0; c < 3; c++) {
                        float wv = ws[((size_t)c * 64 + ci) * 64 + kd * 16 + kh * 4 + kw];
                        u64 w2 = pack2(wv, wv);
#pragma unroll
                        for (int j = 0; j < 4; j++) fma2(acc[c][j], v2[j], w2);
                    }
                }
            }
        }
    }

#pragma unroll
    for (int c = 0; c < 3; c++) {
        float bv = bias[c];
        size_t base = (((size_t)b * 3 + c) * 61 + z) * 61 * 61 + (size_t)y * 61;
#pragma unroll
        for (int j = 0; j < 4; j++) {
            float2 r = unpack2(acc[c][j]);
            int x = x0 + 2 * j;
            if (x < 61)     out[base + x]     = tanhf(r.x + bv);
            if (x + 1 < 61) out[base + x + 1] = tanhf(r.y + bv);
        }
    }
}

// ---------------------------------------------------------------------------

extern "C" void kernel_launch(void* const* d_in, const int* in_sizes, int n_in,
                              void* d_out, int out_size)
{
    const float* x   = (const float*)d_in[0];
    const float* ew1 = (const float*)d_in[1];  const float* eb1 = (const float*)d_in[2];
    const float* ew2 = (const float*)d_in[3];  const float* eb2 = (const float*)d_in[4];
    const float* ew3 = (const float*)d_in[5];  const float* eb3 = (const float*)d_in[6];
    const float* ew4 = (const float*)d_in[7];  const float* eb4 = (const float*)d_in[8];
    const float* cb  = (const float*)d_in[9];
    const float* dw1 = (const float*)d_in[10]; const float* db1 = (const float*)d_in[11];
    const float* dw2 = (const float*)d_in[12]; const float* db2 = (const float*)d_in[13];
    const float* dw3 = (const float*)d_in[14]; const float* db3 = (const float*)d_in[15];
    const float* dw4 = (const float*)d_in[16]; const float* db4 = (const float*)d_in[17];

    float* out = (float*)d_out;
    const int RECON = 2 * 3 * 61 * 61 * 61;  // 1361886
    float* idx_out = (out_size >= RECON + 1024) ? (out + RECON) : nullptr;

    float *h1, *h2, *h3, *lat, *q, *d1, *d2, *d3;
    cudaGetSymbolAddress((void**)&h1, g_h1);
    cudaGetSymbolAddress((void**)&h2, g_h2);
    cudaGetSymbolAddress((void**)&h3, g_h3);
    cudaGetSymbolAddress((void**)&lat, g_lat);
    cudaGetSymbolAddress((void**)&q, g_q);
    cudaGetSymbolAddress((void**)&d1, g_d1);
    cudaGetSymbolAddress((void**)&d2, g_d2);
    cudaGetSymbolAddress((void**)&d3, g_d3);

    // encoder
    conv_s2_relu<3, 64, 32, 8><<<dim3(64, 8, 2), 128>>>(x, ew1, eb1, h1);
    conv_s2_relu<64, 128, 16, 8><<<dim3(8, 16, 2), 128>>>(h1, ew2, eb2, h2);
    conv_s2_relu<128, 256, 8, 4><<<dim3(1, 64, 2), 128>>>(h2, ew3, eb3, h3);
    conv1x1<<<dim3(4, 32, 2), 128>>>(h3, ew4, eb4, lat);

    // vector quantization (also writes idx tail of output)
    vq_kernel<<<128, 128>>>(lat, cb, q, idx_out);

    // decoder
    convT_relu<256, 256, 8, 8><<<dim3(1, 32, 16), 128>>>(q, dw1, db1, d1);
    convT_relu<256, 128, 16, 8><<<dim3(8, 16, 16), 128>>>(d1, dw2, db2, d2);
    convT_relu<128, 64, 32, 8><<<dim3(64, 8, 16), 128>>>(d2, dw3, db3, d3);
    conv_final_tanh<<<dim3(4, 61, 2), 128>>>(d3, dw4, db4, out);
}

// round 5
// speedup vs baseline: 1.6242x; 1.6242x over previous
#include <cuda_runtime.h>
#include <cuda_bf16.h>
#include <math.h>
#include <cfloat>

// ---------------------------------------------------------------------------
// VQGAN forward. dec2/dec3 (75% of FLOPs) via mma.sync bf16 (2-term split,
// fp32 accumulate). Everything else: round-1 scalar kernels.
// ---------------------------------------------------------------------------

#define NB 2

__device__ float g_h1[(size_t)NB * 64 * 32 * 32 * 32];
__device__ float g_h2[(size_t)NB * 128 * 16 * 16 * 16];
__device__ float g_h3[(size_t)NB * 256 * 8 * 8 * 8];
__device__ float g_lat[(size_t)NB * 256 * 512];
__device__ float g_q[(size_t)NB * 256 * 512];
__device__ float g_d1[(size_t)NB * 256 * 16 * 16 * 16];
__device__ float g_d2[(size_t)NB * 128 * 32 * 32 * 32];
__device__ float g_d3[(size_t)NB * 64 * 64 * 64 * 64];

// ---- helpers ---------------------------------------------------------------
__device__ __forceinline__ unsigned ldp(unsigned a) {   // two adjacent bf16 -> b32
    unsigned r;
    asm volatile("{\n\t.reg .b16 l, h;\n\t"
                 "ld.shared.b16 l, [%1];\n\t"
                 "ld.shared.b16 h, [%1+2];\n\t"
                 "mov.b32 %0, {l, h};\n\t}"
                 : "=r"(r) : "r"(a));
    return r;
}
__device__ __forceinline__ unsigned pack_bf16(float a, float b) {
    __nv_bfloat162 t = __floats2bfloat162_rn(a, b);
    return *reinterpret_cast<unsigned*>(&t);
}
__device__ __forceinline__ void mma16816(float* c, const unsigned* a, const unsigned* b) {
    asm volatile("mma.sync.aligned.m16n8k16.row.col.f32.bf16.bf16.f32 "
                 "{%0,%1,%2,%3},{%4,%5,%6,%7},{%8,%9},{%0,%1,%2,%3};"
                 : "+f"(c[0]), "+f"(c[1]), "+f"(c[2]), "+f"(c[3])
                 : "r"(a[0]), "r"(a[1]), "r"(a[2]), "r"(a[3]),
                   "r"(b[0]), "r"(b[1]));
}

// ---------------------------------------------------------------------------
// convT k4 s2 p1 + ReLU via tensor cores.
// Per (batch, parity class): GEMM  M=Din^3 (output pre-up positions),
// N=Cout, K=Cin*8 taps. K order: ci_sub*8 + (tz,ty)*2 + e, where the e-pair
// maps to x-adjacent ascending input elements (class-dependent weight perm).
// CTA: M=128 x N=64, 8 warps (4Mx2N), K16 per iter (2 ci), double-buffered.
// ---------------------------------------------------------------------------
template <int Cin, int Cout, int Din>
__global__ void __launch_bounds__(256)
convT_mma(const float* __restrict__ in, const float* __restrict__ w,
          const float* __restrict__ bias, float* __restrict__ out)
{
    constexpr int Dout = 2 * Din;
    constexpr int R = 128 / Din;            // x-rows per M-tile
    constexpr int XS = Din + 2;             // x extent with halo
    constexpr int YS = R + 2;               // y extent with halo
    constexpr int ZS = YS * XS;
    constexpr int CIS = 2 * ZS;             // per-ci raw-tile stride (2 z planes)
    constexpr int RAWN = 2 * CIS;           // 2 ci
    constexpr int NIT = Cin / 2;
    constexpr int LDRS = (RAWN + 255) / 256;
    constexpr int BP = 9;                   // padded B pitch (conflict-free)
    constexpr int TPP = (Din * Din) / 128;  // M-tiles per z-plane
    constexpr size_t D3 = (size_t)Din * Din * Din;

    __shared__ __nv_bfloat16 rawHi[2][RAWN];
    __shared__ __nv_bfloat16 rawLo[2][RAWN];
    __shared__ unsigned Bh_s[2][64 * BP];
    __shared__ unsigned Bl_s[2][64 * BP];

    const int tid = threadIdx.x, lane = tid & 31, wid = tid >> 5;
    const int wm = wid & 3, wn = wid >> 2;
    const int bzz = blockIdx.z, bb = bzz >> 3, cls = bzz & 7;
    const int rz = (cls >> 2) & 1, ry = (cls >> 1) & 1, rx = cls & 1;
    const int zoff1 = rz ? 1 : -1, yoff1 = ry ? 1 : -1;
    const int mz = blockIdx.x / TPP;
    const int my0 = (blockIdx.x % TPP) * R;
    const int coBase = blockIdx.y * 64;

    // ---- raw-tile staging descriptors (fixed per thread across K loop) ----
    size_t rs_goff[LDRS];
    int rs_i[LDRS];
    bool rs_ok[LDRS], rs_act[LDRS];
#pragma unroll
    for (int l = 0; l < LDRS; l++) {
        int i = tid + l * 256;
        bool act = (i < RAWN);
        int ii = act ? i : 0;
        int ci_sub = ii / CIS;
        int r1 = ii % CIS;
        int tz = r1 / ZS;
        int r2 = r1 % ZS;
        int yy = r2 / XS, xx = r2 % XS;
        int gz = mz + (tz ? zoff1 : 0);
        int gy = my0 + yy - 1;
        int gx = xx - 1;
        bool ok = act && (unsigned)gz < (unsigned)Din &&
                  (unsigned)gy < (unsigned)Din && (unsigned)gx < (unsigned)Din;
        rs_goff[l] = ok ? ((((size_t)bb * Cin + ci_sub) * Din + gz) * (Din * Din)
                           + (size_t)gy * Din + gx)
                        : 0;
        rs_i[l] = ii;
        rs_ok[l] = ok;
        rs_act[l] = act;
    }

    // ---- weight staging descriptors (class-permuted fragment layout) ----
    size_t ws_g0[2], ws_g1[2];
    int ws_i[2];
#pragma unroll
    for (int l = 0; l < 2; l++) {
        int q = tid + l * 256;          // 0..511 pair slots
        int co = q >> 3, p = q & 7;
        int ci_sub = p >> 2, kpw = p & 3, tz = kpw >> 1, ty = kpw & 1;
        int kd = rz ? 2 - 2 * tz : 1 + 2 * tz;
        int kh = ry ? 2 - 2 * ty : 1 + 2 * ty;
        int kw0 = rx ? 2 : 3;           // k even  <-> lower x
        int kw1 = rx ? 0 : 1;           // k odd   <-> higher x
        size_t base = ((size_t)ci_sub * Cout + coBase + co) * 64 + kd * 16 + kh * 4;
        ws_g0[l] = base + kw0;
        ws_g1[l] = base + kw1;
        ws_i[l] = co * BP + p;
    }

    // ---- A fragment smem offsets (elements) ----
    const int kp = lane & 3, tzk = kp >> 1, tyk = kp & 1;
    int aoff[2][2];
#pragma unroll
    for (int t = 0; t < 2; t++)
#pragma unroll
        for (int h = 0; h < 2; h++) {
            int mloc = wm * 32 + t * 16 + (lane >> 2) + h * 8;
            int myl = mloc / Din, mx = mloc % Din;
            int yy = myl + (tyk ? yoff1 : 0) + 1;
            aoff[t][h] = tzk * ZS + yy * XS + mx + rx;
        }
    const unsigned shHi = (unsigned)__cvta_generic_to_shared(&rawHi[0][0]);
    const unsigned shLo = (unsigned)__cvta_generic_to_shared(&rawLo[0][0]);

    int boff[4];
#pragma unroll
    for (int j = 0; j < 4; j++)
        boff[j] = (wn * 32 + j * 8 + (lane >> 2)) * BP + (lane & 3);

    float C[2][4][4];
#pragma unroll
    for (int t = 0; t < 2; t++)
#pragma unroll
        for (int j = 0; j < 4; j++)
#pragma unroll
            for (int k = 0; k < 4; k++) C[t][j][k] = 0.f;

    // ---- pipelined main loop ----
    float rv[LDRS], wa[2], wc[2];

#define STAGE_REGS(IT)                                                          \
    {                                                                           \
        size_t cioff = (size_t)(2 * (IT)) * D3;                                 \
        _Pragma("unroll")                                                       \
        for (int l = 0; l < LDRS; l++)                                          \
            rv[l] = rs_ok[l] ? __ldg(in + rs_goff[l] + cioff) : 0.f;            \
        size_t woff = (size_t)(2 * (IT)) * Cout * 64;                           \
        _Pragma("unroll")                                                       \
        for (int l = 0; l < 2; l++) {                                           \
            wa[l] = __ldg(w + ws_g0[l] + woff);                                 \
            wc[l] = __ldg(w + ws_g1[l] + woff);                                 \
        }                                                                       \
    }

#define STAGE_STORE(BF)                                                         \
    {                                                                           \
        _Pragma("unroll")                                                       \
        for (int l = 0; l < LDRS; l++)                                          \
            if (rs_act[l]) {                                                    \
                float v = rv[l];                                                \
                __nv_bfloat16 h = __float2bfloat16_rn(v);                       \
                rawHi[BF][rs_i[l]] = h;                                         \
                rawLo[BF][rs_i[l]] = __float2bfloat16_rn(v - __bfloat162float(h)); \
            }                                                                   \
        _Pragma("unroll")                                                       \
        for (int l = 0; l < 2; l++) {                                           \
            float a = wa[l], c = wc[l];                                         \
            float ah = __bfloat162float(__float2bfloat16_rn(a));                \
            float ch = __bfloat162float(__float2bfloat16_rn(c));                \
            Bh_s[BF][ws_i[l]] = pack_bf16(a, c);                                \
            Bl_s[BF][ws_i[l]] = pack_bf16(a - ah, c - ch);                      \
        }                                                                       \
    }

#define COMPUTE(BF)                                                             \
    {                                                                           \
        unsigned hb = shHi + (BF) * (RAWN * 2);                                 \
        unsigned lb = shLo + (BF) * (RAWN * 2);                                 \
        unsigned Ah[2][4], Al[2][4];                                            \
        _Pragma("unroll")                                                       \
        for (int t = 0; t < 2; t++) {                                           \
            unsigned o0 = aoff[t][0] * 2, o1 = aoff[t][1] * 2;                  \
            Ah[t][0] = ldp(hb + o0);                                            \
            Ah[t][1] = ldp(hb + o1);                                            \
            Ah[t][2] = ldp(hb + o0 + CIS * 2);                                  \
            Ah[t][3] = ldp(hb + o1 + CIS * 2);                                  \
            Al[t][0] = ldp(lb + o0);                                            \
            Al[t][1] = ldp(lb + o1);                                            \
            Al[t][2] = ldp(lb + o0 + CIS * 2);                                  \
            Al[t][3] = ldp(lb + o1 + CIS * 2);                                  \
        }                                                                       \
        unsigned Bh[4][2], Bl[4][2];                                            \
        _Pragma("unroll")                                                       \
        for (int j = 0; j < 4; j++) {                                           \
            Bh[j][0] = Bh_s[BF][boff[j]];                                       \
            Bh[j][1] = Bh_s[BF][boff[j] + 4];                                   \
            Bl[j][0] = Bl_s[BF][boff[j]];                                       \
            Bl[j][1] = Bl_s[BF][boff[j] + 4];                                   \
        }                                                                       \
        _Pragma("unroll")                                                       \
        for (int t = 0; t < 2; t++)                                             \
            _Pragma("unroll")                                                   \
            for (int j = 0; j < 4; j++) {                                       \
                mma16816(C[t][j], Ah[t], Bh[j]);                                \
                mma16816(C[t][j], Ah[t], Bl[j]);                                \
                mma16816(C[t][j], Al[t], Bh[j]);                                \
            }                                                                   \
    }

    STAGE_REGS(0);
    STAGE_STORE(0);
    __syncthreads();

    int bf = 0;
    for (int it = 0; it < NIT; ++it) {
        bool more = (it + 1 < NIT);
        if (more) STAGE_REGS(it + 1);
        COMPUTE(bf);
        if (more) {
            STAGE_STORE(bf ^ 1);
            bf ^= 1;
            __syncthreads();
        }
    }

#undef STAGE_REGS
#undef STAGE_STORE
#undef COMPUTE

    // ---- epilogue: bias + ReLU + scattered store ----
    const int oz = 2 * mz + rz;
#pragma unroll
    for (int j = 0; j < 4; j++) {
        int n0 = coBase + wn * 32 + j * 8 + (lane & 3) * 2;
        float bv0 = bias[n0], bv1 = bias[n0 + 1];
#pragma unroll
        for (int t = 0; t < 2; t++)
#pragma unroll
            for (int h = 0; h < 2; h++) {
                int mloc = wm * 32 + t * 16 + (lane >> 2) + h * 8;
                int my = my0 + mloc / Din, mx = mloc % Din;
                int oy = 2 * my + ry, ox = 2 * mx + rx;
                size_t a = (((size_t)bb * Cout + n0) * Dout + oz) * ((size_t)Dout * Dout)
                           + (size_t)oy * Dout + ox;
                out[a] = fmaxf(C[t][j][2 * h] + bv0, 0.f);
                out[a + (size_t)Dout * Dout * Dout] = fmaxf(C[t][j][2 * h + 1] + bv1, 0.f);
            }
    }
}

// ---------------------------------------------------------------------------
// Round-1 scalar kernels for everything else.
// ---------------------------------------------------------------------------
template <int Cin, int Cout, int Dout>
__global__ void conv_s2_relu(const float* __restrict__ in,
                             const float* __restrict__ w,
                             const float* __restrict__ bias,
                             float* __restrict__ out)
{
    constexpr int Din = 2 * Dout;
    constexpr int CI_CHUNK = (Cin < 16) ? Cin : 16;
    __shared__ float ws[CI_CHUNK][8][64];

    const int tid = threadIdx.x;
    const int coBase = blockIdx.y * 8;
    const int b = blockIdx.z;
    const int s0 = blockIdx.x * 512 + tid * 4;
    const int ox0 = s0 % Dout;
    const int oy = (s0 / Dout) % Dout;
    const int oz = s0 / (Dout * Dout);

    float acc[4][8];
#pragma unroll
    for (int p = 0; p < 4; p++)
#pragma unroll
        for (int c = 0; c < 8; c++) acc[p][c] = 0.f;

    const float* inB = in + (size_t)b * Cin * Din * Din * Din;

    for (int ci0 = 0; ci0 < Cin; ci0 += CI_CHUNK) {
        const int nload = CI_CHUNK * 8 * 64;
        for (int i = tid; i < nload; i += 128) {
            int ci = i / (8 * 64);
            int rem = i % (8 * 64);
            int co = rem / 64;
            int tap = rem % 64;
            ws[ci][co][tap] = w[((size_t)(coBase + co) * Cin + (ci0 + ci)) * 64 + tap];
        }
        __syncthreads();

#pragma unroll 1
        for (int ci = 0; ci < CI_CHUNK; ci++) {
            const float* inC = inB + (size_t)(ci0 + ci) * Din * Din * Din;
#pragma unroll
            for (int kd = 0; kd < 4; kd++) {
                const int iz = 2 * oz + kd - 1;
                if ((unsigned)iz >= (unsigned)Din) continue;
#pragma unroll
                for (int kh = 0; kh < 4; kh++) {
                    const int iy = 2 * oy + kh - 1;
                    if ((unsigned)iy >= (unsigned)Din) continue;
                    const float* row = inC + (size_t)iz * Din * Din + (size_t)iy * Din;
#pragma unroll
                    for (int kw = 0; kw < 4; kw++) {
                        const int ixb = 2 * ox0 + kw - 1;
                        float v[4];
#pragma unroll
                        for (int p = 0; p < 4; p++) {
                            int ix = ixb + 2 * p;
                            v[p] = ((unsigned)ix < (unsigned)Din) ? row[ix] : 0.f;
                        }
                        const int tap = kd * 16 + kh * 4 + kw;
#pragma unroll
                        for (int c = 0; c < 8; c++) {
                            float wv = ws[ci][c][tap];
#pragma unroll
                            for (int p = 0; p < 4; p++) acc[p][c] += v[p] * wv;
                        }
                    }
                }
            }
        }
        __syncthreads();
    }

#pragma unroll
    for (int c = 0; c < 8; c++) {
        float bv = bias[coBase + c];
        size_t base = (((size_t)b * Cout + coBase + c) * Dout + oz) * Dout * Dout
                      + (size_t)oy * Dout + ox0;
#pragma unroll
        for (int p = 0; p < 4; p++) out[base + p] = fmaxf(acc[p][c] + bv, 0.f);
    }
}

__global__ void conv1x1(const float* __restrict__ in, const float* __restrict__ w,
                        const float* __restrict__ bias, float* __restrict__ out)
{
    __shared__ float ws[8][256];
    const int tid = threadIdx.x;
    const int coBase = blockIdx.y * 8;
    const int b = blockIdx.z;
    const int s = blockIdx.x * 128 + tid;

    for (int i = tid; i < 8 * 256; i += 128)
        ws[i / 256][i % 256] = w[(size_t)(coBase + i / 256) * 256 + (i % 256)];
    __syncthreads();

    float acc[8];
#pragma unroll
    for (int c = 0; c < 8; c++) acc[c] = 0.f;

    const float* inB = in + (size_t)b * 256 * 512 + s;
    for (int ci = 0; ci < 256; ci++) {
        float v = inB[(size_t)ci * 512];
#pragma unroll
        for (int c = 0; c < 8; c++) acc[c] += v * ws[c][ci];
    }
#pragma unroll
    for (int c = 0; c < 8; c++)
        out[((size_t)b * 256 + coBase + c) * 512 + s] = acc[c] + bias[coBase + c];
}

__global__ void vq_kernel(const float* __restrict__ lat, const float* __restrict__ cb,
                          float* __restrict__ q, float* __restrict__ idx_out)
{
    __shared__ float4 latS[8][64];
    __shared__ float ln[8];
    __shared__ float bd[8][128];
    __shared__ int bk[8][128];
    __shared__ int wink[8];

    const int tid = threadIdx.x;
    const int vb = blockIdx.x * 8;

    for (int i = tid; i < 8 * 64; i += 128) {
        int v = i >> 6, d4 = i & 63;
        latS[v][d4] = ((const float4*)lat)[(size_t)(vb + v) * 64 + d4];
    }
    __syncthreads();

    if (tid < 8) {
        float s = 0.f;
        for (int d4 = 0; d4 < 64; d4++) {
            float4 l = latS[tid][d4];
            s += l.x * l.x + l.y * l.y + l.z * l.z + l.w * l.w;
        }
        ln[tid] = s;
    }
    __syncthreads();

    float best[8];
    int bestk[8];
#pragma unroll
    for (int v = 0; v < 8; v++) { best[v] = FLT_MAX; bestk[v] = 0; }

    for (int j = 0; j < 8; j++) {
        const int k = tid + j * 128;
        const float4* cbr = (const float4*)(cb + (size_t)k * 256);
        float dot[8];
        float cn = 0.f;
#pragma unroll
        for (int v = 0; v < 8; v++) dot[v] = 0.f;
        for (int d4 = 0; d4 < 64; d4++) {
            float4 c = cbr[d4];
            cn += c.x * c.x + c.y * c.y + c.z * c.z + c.w * c.w;
#pragma unroll
            for (int v = 0; v < 8; v++) {
                float4 l = latS[v][d4];
                dot[v] += c.x * l.x + c.y * l.y + c.z * l.z + c.w * l.w;
            }
        }
#pragma unroll
        for (int v = 0; v < 8; v++) {
            float d2 = ln[v] - 2.f * dot[v] + cn;
            if (d2 < best[v]) { best[v] = d2; bestk[v] = k; }
        }
    }

#pragma unroll
    for (int v = 0; v < 8; v++) { bd[v][tid] = best[v]; bk[v][tid] = bestk[v]; }
    __syncthreads();
    for (int s = 64; s > 0; s >>= 1) {
        if (tid < s) {
#pragma unroll
            for (int v = 0; v < 8; v++) {
                float dB = bd[v][tid + s];
                int kB = bk[v][tid + s];
                float dA = bd[v][tid];
                int kA = bk[v][tid];
                if (dB < dA || (dB == dA && kB < kA)) { bd[v][tid] = dB; bk[v][tid] = kB; }
            }
        }
        __syncthreads();
    }
    if (tid < 8) {
        wink[tid] = bk[tid][0];
        if (idx_out) idx_out[vb + tid] = (float)bk[tid][0];
    }
    __syncthreads();

    for (int i = tid; i < 8 * 256; i += 128) {
        int v = i >> 8, c = i & 255;
        int gn = vb + v;
        int b = gn >> 9, n = gn & 511;
        q[((size_t)b * 256 + c) * 512 + n] = cb[(size_t)wink[v] * 256 + c];
    }
}

__device__ __forceinline__ int kparity(int r, int t) { return r ? (2 - 2 * t) : (1 + 2 * t); }

template <int Cin, int Cout, int Din>
__global__ void convT_relu(const float* __restrict__ in, const float* __restrict__ w,
                           const float* __restrict__ bias, float* __restrict__ out)
{
    constexpr int Dout = 2 * Din;
    constexpr int CI_CHUNK = 16;
    __shared__ float ws[CI_CHUNK][8][8];

    const int tid = threadIdx.x;
    const int coBase = blockIdx.y * 8;
    const int bz = blockIdx.z;
    const int b = bz >> 3;
    const int cls = bz & 7;
    const int rz = (cls >> 2) & 1, ry = (cls >> 1) & 1, rx = cls & 1;

    const int zoff1 = rz ? 1 : -1;
    const int yoff1 = ry ? 1 : -1;
    const int xoff1 = rx ? 1 : -1;

    const int m0 = blockIdx.x * 512 + tid * 4;
    const int mx0 = m0 % Din;
    const int my = (m0 / Din) % Din;
    const int mz = m0 / (Din * Din);

    float acc[4][8];
#pragma unroll
    for (int p = 0; p < 4; p++)
#pragma unroll
        for (int c = 0; c < 8; c++) acc[p][c] = 0.f;

    const float* inB = in + (size_t)b * Cin * Din * Din * Din;

    for (int ci0 = 0; ci0 < Cin; ci0 += CI_CHUNK) {
        for (int i = tid; i < CI_CHUNK * 64; i += 128) {
            int ci = i / 64;
            int rem = i % 64;
            int co = rem / 8;
            int t = rem % 8;
            int tz = (t >> 2) & 1, ty = (t >> 1) & 1, tx = t & 1;
            int tap = kparity(rz, tz) * 16 + kparity(ry, ty) * 4 + kparity(rx, tx);
            ws[ci][co][t] = w[((size_t)(ci0 + ci) * Cout + coBase + co) * 64 + tap];
        }
        __syncthreads();

#pragma unroll 1
        for (int ci = 0; ci < CI_CHUNK; ci++) {
            const float* inC = inB + (size_t)(ci0 + ci) * Din * Din * Din;
#pragma unroll
            for (int tz = 0; tz < 2; tz++) {
                const int iz = mz + (tz ? zoff1 : 0);
                if ((unsigned)iz >= (unsigned)Din) continue;
#pragma unroll
                for (int ty = 0; ty < 2; ty++) {
                    const int iy = my + (ty ? yoff1 : 0);
                    if ((unsigned)iy >= (unsigned)Din) continue;
                    const float* row = inC + (size_t)iz * Din * Din + (size_t)iy * Din;
#pragma unroll
                    for (int tx = 0; tx < 2; tx++) {
                        const int xo = tx ? xoff1 : 0;
                        float v[4];
#pragma unroll
                        for (int p = 0; p < 4; p++) {
                            int ix = mx0 + p + xo;
                            v[p] = ((unsigned)ix < (unsigned)Din) ? row[ix] : 0.f;
                        }
                        const int t = tz * 4 + ty * 2 + tx;
#pragma unroll
                        for (int c = 0; c < 8; c++) {
                            float wv = ws[ci][c][t];
#pragma unroll
                            for (int p = 0; p < 4; p++) acc[p][c] += v[p] * wv;
                        }
                    }
                }
            }
        }
        __syncthreads();
    }

    const int oz = 2 * mz + rz;
    const int oy = 2 * my + ry;
#pragma unroll
    for (int c = 0; c < 8; c++) {
        float bv = bias[coBase + c];
        size_t base = (((size_t)b * Cout + coBase + c) * Dout + oz) * Dout * Dout
                      + (size_t)oy * Dout;
#pragma unroll
        for (int p = 0; p < 4; p++) {
            int ox = 2 * (mx0 + p) + rx;
            out[base + ox] = fmaxf(acc[p][c] + bv, 0.f);
        }
    }
}

__global__ void conv_final_tanh(const float* __restrict__ in, const float* __restrict__ w,
                                const float* __restrict__ bias, float* __restrict__ out)
{
    __shared__ float ws[3 * 64 * 64];
    const int tid = threadIdx.x;
    for (int i = tid; i < 3 * 64 * 64; i += 128) ws[i] = w[i];
    __syncthreads();

    const int b = blockIdx.z;
    const int z = blockIdx.y;
    const int ry = tid / 16;
    const int quad = tid % 16;
    const int y = blockIdx.x * 8 + ry;
    const int x0 = quad * 4;
    if (y >= 61) return;

    float acc[3][4];
#pragma unroll
    for (int c = 0; c < 3; c++)
#pragma unroll
        for (int p = 0; p < 4; p++) acc[c][p] = 0.f;

    const float* inB = in + (size_t)b * 64 * 64 * 64 * 64;
#pragma unroll 1
    for (int ci = 0; ci < 64; ci++) {
        const float* inC = inB + (size_t)ci * 262144;
#pragma unroll
        for (int kd = 0; kd < 4; kd++) {
            const float* pz = inC + (size_t)(z + kd) * 4096;
#pragma unroll
            for (int kh = 0; kh < 4; kh++) {
                const float* row = pz + (size_t)(y + kh) * 64;
                float v[7];
#pragma unroll
                for (int j = 0; j < 7; j++) {
                    int ix = x0 + j;
                    v[j] = (ix < 64) ? row[ix] : 0.f;
                }
#pragma unroll
                for (int kw = 0; kw < 4; kw++) {
#pragma unroll
                    for (int c = 0; c < 3; c++) {
                        float wv = ws[((size_t)c * 64 + ci) * 64 + kd * 16 + kh * 4 + kw];
#pragma unroll
                        for (int p = 0; p < 4; p++) acc[c][p] += v[kw + p] * wv;
                    }
                }
            }
        }
    }

#pragma unroll
    for (int c = 0; c < 3; c++) {
        float bv = bias[c];
        size_t base = (((size_t)b * 3 + c) * 61 + z) * 61 * 61 + (size_t)y * 61;
#pragma unroll
        for (int p = 0; p < 4; p++) {
            int x = x0 + p;
            if (x < 61) out[base + x] = tanhf(acc[c][p] + bv);
        }
    }
}

// ---------------------------------------------------------------------------

extern "C" void kernel_launch(void* const* d_in, const int* in_sizes, int n_in,
                              void* d_out, int out_size)
{
    const float* x   = (const float*)d_in[0];
    const float* ew1 = (const float*)d_in[1];  const float* eb1 = (const float*)d_in[2];
    const float* ew2 = (const float*)d_in[3];  const float* eb2 = (const float*)d_in[4];
    const float* ew3 = (const float*)d_in[5];  const float* eb3 = (const float*)d_in[6];
    const float* ew4 = (const float*)d_in[7];  const float* eb4 = (const float*)d_in[8];
    const float* cb  = (const float*)d_in[9];
    const float* dw1 = (const float*)d_in[10]; const float* db1 = (const float*)d_in[11];
    const float* dw2 = (const float*)d_in[12]; const float* db2 = (const float*)d_in[13];
    const float* dw3 = (const float*)d_in[14]; const float* db3 = (const float*)d_in[15];
    const float* dw4 = (const float*)d_in[16]; const float* db4 = (const float*)d_in[17];

    float* out = (float*)d_out;
    const int RECON = 2 * 3 * 61 * 61 * 61;
    float* idx_out = (out_size >= RECON + 1024) ? (out + RECON) : nullptr;

    float *h1, *h2, *h3, *lat, *q, *d1, *d2, *d3;
    cudaGetSymbolAddress((void**)&h1, g_h1);
    cudaGetSymbolAddress((void**)&h2, g_h2);
    cudaGetSymbolAddress((void**)&h3, g_h3);
    cudaGetSymbolAddress((void**)&lat, g_lat);
    cudaGetSymbolAddress((void**)&q, g_q);
    cudaGetSymbolAddress((void**)&d1, g_d1);
    cudaGetSymbolAddress((void**)&d2, g_d2);
    cudaGetSymbolAddress((void**)&d3, g_d3);

    // encoder (scalar, round-1)
    conv_s2_relu<3, 64, 32><<<dim3(64, 8, 2), 128>>>(x, ew1, eb1, h1);
    conv_s2_relu<64, 128, 16><<<dim3(8, 16, 2), 128>>>(h1, ew2, eb2, h2);
    conv_s2_relu<128, 256, 8><<<dim3(1, 32, 2), 128>>>(h2, ew3, eb3, h3);
    conv1x1<<<dim3(4, 32, 2), 128>>>(h3, ew4, eb4, lat);

    // vector quantization
    vq_kernel<<<128, 128>>>(lat, cb, q, idx_out);

    // decoder: dec1 scalar, dec2/dec3 tensor-core, dec4 scalar
    convT_relu<256, 256, 8><<<dim3(1, 32, 16), 128>>>(q, dw1, db1, d1);
    convT_mma<256, 128, 16><<<dim3(32, 2, 16), 256>>>(d1, dw2, db2, d2);
    convT_mma<128, 64, 32><<<dim3(256, 1, 16), 256>>>(d2, dw3, db3, d3);
    conv_final_tanh<<<dim3(8, 61, 2), 128>>>(d3, dw4, db4, out);
}

// round 6
// speedup vs baseline: 1.8589x; 1.1445x over previous
#include <cuda_runtime.h>
#include <cuda_bf16.h>
#include <math.h>
#include <cfloat>

// ---------------------------------------------------------------------------
// VQGAN forward. dec2/dec3 via mma.sync bf16 (2-term split, fp32 accumulate),
// K ordered as (tap, ci-pair) so all fragments are aligned LDS.32.
// Everything else: round-1 scalar kernels.
// ---------------------------------------------------------------------------

#define NB 2

__device__ float g_h1[(size_t)NB * 64 * 32 * 32 * 32];
__device__ float g_h2[(size_t)NB * 128 * 16 * 16 * 16];
__device__ float g_h3[(size_t)NB * 256 * 8 * 8 * 8];
__device__ float g_lat[(size_t)NB * 256 * 512];
__device__ float g_q[(size_t)NB * 256 * 512];
__device__ float g_d1[(size_t)NB * 256 * 16 * 16 * 16];
__device__ float g_d2[(size_t)NB * 128 * 32 * 32 * 32];
__device__ float g_d3[(size_t)NB * 64 * 64 * 64 * 64];

// ---- helpers ---------------------------------------------------------------
__device__ __forceinline__ unsigned pack_bf16(float a, float b) {
    __nv_bfloat162 t = __floats2bfloat162_rn(a, b);   // low = a, high = b
    return *reinterpret_cast<unsigned*>(&t);
}
__device__ __forceinline__ void mma16816(float* c, const unsigned* a, const unsigned* b) {
    asm volatile("mma.sync.aligned.m16n8k16.row.col.f32.bf16.bf16.f32 "
                 "{%0,%1,%2,%3},{%4,%5,%6,%7},{%8,%9},{%0,%1,%2,%3};"
                 : "+f"(c[0]), "+f"(c[1]), "+f"(c[2]), "+f"(c[3])
                 : "r"(a[0]), "r"(a[1]), "r"(a[2]), "r"(a[3]),
                   "r"(b[0]), "r"(b[1]));
}
__device__ __forceinline__ int kparity(int r, int t) { return r ? (2 - 2 * t) : (1 + 2 * t); }

// ---------------------------------------------------------------------------
// convT k4 s2 p1 + ReLU via tensor cores.
// GEMM per (batch, parity class): M = Din^3, N = Cout, K = 8 taps x Cin.
// k16 block = 8 taps x 2 ci; k-pair (2j,2j+1) = tap j, channels (ci0, ci0+1).
// Input tile staged as b32 words {v_ci0, v_ci1} over halo spatial positions;
// weights as b32 words {w_ci0, w_ci1} per (co, tap). All fragment loads are
// aligned LDS.32. CTA: M=128 x N=64, 8 warps (4Mx2N), double-buffered.
// ---------------------------------------------------------------------------
template <int Cin, int Cout, int Din>
__global__ void __launch_bounds__(256)
convT_mma(const float* __restrict__ in, const float* __restrict__ w,
          const float* __restrict__ bias, float* __restrict__ out)
{
    constexpr int Dout = 2 * Din;
    constexpr int R = 128 / Din;            // y-rows per M-tile
    constexpr int XS = Din + 2;             // x extent with halo
    constexpr int YS = R + 2;               // y extent with halo
    constexpr int ZS = YS * XS;             // words per tz plane
    constexpr int TW = 2 * ZS;              // tile words (2 tz planes)
    constexpr int NIT = Cin / 2;
    constexpr int LDW = (TW + 255) / 256;
    constexpr int BP = 9;                   // padded B pitch
    constexpr int TPP = (Din * Din) / 128;  // M-tiles per z-plane
    constexpr size_t D3 = (size_t)Din * Din * Din;

    __shared__ unsigned rawHi[2][TW];
    __shared__ unsigned rawLo[2][TW];
    __shared__ unsigned Bh_s[2][64 * BP];
    __shared__ unsigned Bl_s[2][64 * BP];

    const int tid = threadIdx.x, lane = tid & 31, wid = tid >> 5;
    const int wm = wid & 3, wn = wid >> 2;
    const int bzz = blockIdx.z, bb = bzz >> 3, cls = bzz & 7;
    const int rz = (cls >> 2) & 1, ry = (cls >> 1) & 1, rx = cls & 1;
    const int zoff1 = rz ? 1 : -1, yoff1 = ry ? 1 : -1, xoff1 = rx ? 1 : -1;
    const int mz = blockIdx.x / TPP;
    const int my0 = (blockIdx.x % TPP) * R;
    const int coBase = blockIdx.y * 64;

    // ---- input-tile staging descriptors (per 32-bit word) ----
    size_t rs_goff[LDW];
    int rs_i[LDW];
    bool rs_ok[LDW], rs_act[LDW];
#pragma unroll
    for (int l = 0; l < LDW; l++) {
        int i = tid + l * 256;
        bool act = (i < TW);
        int ii = act ? i : 0;
        int tz = ii / ZS;
        int r2 = ii % ZS;
        int yy = r2 / XS, xx = r2 % XS;
        int gz = mz + (tz ? zoff1 : 0);
        int gy = my0 + yy - 1;
        int gx = xx - 1;
        bool ok = act && (unsigned)gz < (unsigned)Din &&
                  (unsigned)gy < (unsigned)Din && (unsigned)gx < (unsigned)Din;
        rs_goff[l] = ok ? (((size_t)bb * Cin * Din + (size_t)gz) * (Din * Din)
                           + (size_t)gy * Din + gx)
                        : 0;
        rs_i[l] = ii;
        rs_ok[l] = ok;
        rs_act[l] = act;
    }

    // ---- weight staging descriptors: slot = (co, tap) ----
    size_t ws_g[2];
    int ws_i[2];
#pragma unroll
    for (int l = 0; l < 2; l++) {
        int q = tid + l * 256;          // 0..511
        int co = q >> 3, t = q & 7;
        int tz = (t >> 2) & 1, ty = (t >> 1) & 1, tx = t & 1;
        int kd = kparity(rz, tz), kh = kparity(ry, ty), kw = kparity(rx, tx);
        ws_g[l] = (size_t)(coBase + co) * 64 + kd * 16 + kh * 4 + kw;   // ci = 0
        ws_i[l] = co * BP + t;
    }

    // ---- A fragment word offsets: [mtile][rowhalf][khalf] ----
    const int kp = lane & 3;
    int aoff[2][2][2];
#pragma unroll
    for (int t = 0; t < 2; t++)
#pragma unroll
        for (int h = 0; h < 2; h++)
#pragma unroll
            for (int q = 0; q < 2; q++) {
                int tap = kp + 4 * q;
                int tzk = (tap >> 2) & 1, tyk = (tap >> 1) & 1, txk = tap & 1;
                int mloc = wm * 32 + t * 16 + (lane >> 2) + h * 8;
                int myl = mloc / Din, mx = mloc % Din;
                int yy = myl + (tyk ? yoff1 : 0) + 1;
                int xx = mx + (txk ? xoff1 : 0) + 1;
                aoff[t][h][q] = tzk * ZS + yy * XS + xx;
            }

    int boff[4];
#pragma unroll
    for (int j = 0; j < 4; j++)
        boff[j] = (wn * 32 + j * 8 + (lane >> 2)) * BP + kp;

    float C[2][4][4];
#pragma unroll
    for (int t = 0; t < 2; t++)
#pragma unroll
        for (int j = 0; j < 4; j++)
#pragma unroll
            for (int k = 0; k < 4; k++) C[t][j][k] = 0.f;

    // ---- pipelined main loop (2 ci per iter) ----
    float rv0[LDW], rv1[LDW], wa[2], wc[2];

#define STAGE_REGS(IT)                                                          \
    {                                                                           \
        size_t cioff = (size_t)(2 * (IT)) * D3;                                 \
        _Pragma("unroll")                                                       \
        for (int l = 0; l < LDW; l++) {                                         \
            rv0[l] = rs_ok[l] ? __ldg(in + rs_goff[l] + cioff) : 0.f;           \
            rv1[l] = rs_ok[l] ? __ldg(in + rs_goff[l] + cioff + D3) : 0.f;      \
        }                                                                       \
        size_t woff = (size_t)(2 * (IT)) * Cout * 64;                           \
        _Pragma("unroll")                                                       \
        for (int l = 0; l < 2; l++) {                                           \
            wa[l] = __ldg(w + ws_g[l] + woff);                                  \
            wc[l] = __ldg(w + ws_g[l] + woff + (size_t)Cout * 64);              \
        }                                                                       \
    }

#define STAGE_STORE(BF)                                                         \
    {                                                                           \
        _Pragma("unroll")                                                       \
        for (int l = 0; l < LDW; l++)                                           \
            if (rs_act[l]) {                                                    \
                float v0 = rv0[l], v1 = rv1[l];                                 \
                float h0 = __bfloat162float(__float2bfloat16_rn(v0));           \
                float h1 = __bfloat162float(__float2bfloat16_rn(v1));           \
                rawHi[BF][rs_i[l]] = pack_bf16(v0, v1);                         \
                rawLo[BF][rs_i[l]] = pack_bf16(v0 - h0, v1 - h1);               \
            }                                                                   \
        _Pragma("unroll")                                                       \
        for (int l = 0; l < 2; l++) {                                           \
            float a = wa[l], c = wc[l];                                         \
            float ah = __bfloat162float(__float2bfloat16_rn(a));                \
            float ch = __bfloat162float(__float2bfloat16_rn(c));                \
            Bh_s[BF][ws_i[l]] = pack_bf16(a, c);                                \
            Bl_s[BF][ws_i[l]] = pack_bf16(a - ah, c - ch);                      \
        }                                                                       \
    }

#define COMPUTE(BF)                                                             \
    {                                                                           \
        unsigned Ah[2][4], Al[2][4];                                            \
        _Pragma("unroll")                                                       \
        for (int t = 0; t < 2; t++) {                                           \
            Ah[t][0] = rawHi[BF][aoff[t][0][0]];                                \
            Ah[t][1] = rawHi[BF][aoff[t][1][0]];                                \
            Ah[t][2] = rawHi[BF][aoff[t][0][1]];                                \
            Ah[t][3] = rawHi[BF][aoff[t][1][1]];                                \
            Al[t][0] = rawLo[BF][aoff[t][0][0]];                                \
            Al[t][1] = rawLo[BF][aoff[t][1][0]];                                \
            Al[t][2] = rawLo[BF][aoff[t][0][1]];                                \
            Al[t][3] = rawLo[BF][aoff[t][1][1]];                                \
        }                                                                       \
        unsigned Bh[4][2], Bl[4][2];                                            \
        _Pragma("unroll")                                                       \
        for (int j = 0; j < 4; j++) {                                           \
            Bh[j][0] = Bh_s[BF][boff[j]];                                       \
            Bh[j][1] = Bh_s[BF][boff[j] + 4];                                   \
            Bl[j][0] = Bl_s[BF][boff[j]];                                       \
            Bl[j][1] = Bl_s[BF][boff[j] + 4];                                   \
        }                                                                       \
        _Pragma("unroll")                                                       \
        for (int t = 0; t < 2; t++)                                             \
            _Pragma("unroll")                                                   \
            for (int j = 0; j < 4; j++) {                                       \
                mma16816(C[t][j], Ah[t], Bh[j]);                                \
                mma16816(C[t][j], Ah[t], Bl[j]);                                \
                mma16816(C[t][j], Al[t], Bh[j]);                                \
            }                                                                   \
    }

    STAGE_REGS(0);
    STAGE_STORE(0);
    __syncthreads();

    int bf = 0;
    for (int it = 0; it < NIT; ++it) {
        bool more = (it + 1 < NIT);
        if (more) STAGE_REGS(it + 1);
        COMPUTE(bf);
        if (more) {
            STAGE_STORE(bf ^ 1);
            bf ^= 1;
            __syncthreads();
        }
    }

#undef STAGE_REGS
#undef STAGE_STORE
#undef COMPUTE

    // ---- epilogue: bias + ReLU + scattered store ----
    const int oz = 2 * mz + rz;
#pragma unroll
    for (int j = 0; j < 4; j++) {
        int n0 = coBase + wn * 32 + j * 8 + (lane & 3) * 2;
        float bv0 = bias[n0], bv1 = bias[n0 + 1];
#pragma unroll
        for (int t = 0; t < 2; t++)
#pragma unroll
            for (int h = 0; h < 2; h++) {
                int mloc = wm * 32 + t * 16 + (lane >> 2) + h * 8;
                int my = my0 + mloc / Din, mx = mloc % Din;
                int oy = 2 * my + ry, ox = 2 * mx + rx;
                size_t a = (((size_t)bb * Cout + n0) * Dout + oz) * ((size_t)Dout * Dout)
                           + (size_t)oy * Dout + ox;
                out[a] = fmaxf(C[t][j][2 * h] + bv0, 0.f);
                out[a + (size_t)Dout * Dout * Dout] = fmaxf(C[t][j][2 * h + 1] + bv1, 0.f);
            }
    }
}

// ---------------------------------------------------------------------------
// Round-1 scalar kernels for everything else.
// ---------------------------------------------------------------------------
template <int Cin, int Cout, int Dout>
__global__ void conv_s2_relu(const float* __restrict__ in,
                             const float* __restrict__ w,
                             const float* __restrict__ bias,
                             float* __restrict__ out)
{
    constexpr int Din = 2 * Dout;
    constexpr int CI_CHUNK = (Cin < 16) ? Cin : 16;
    __shared__ float ws[CI_CHUNK][8][64];

    const int tid = threadIdx.x;
    const int coBase = blockIdx.y * 8;
    const int b = blockIdx.z;
    const int s0 = blockIdx.x * 512 + tid * 4;
    const int ox0 = s0 % Dout;
    const int oy = (s0 / Dout) % Dout;
    const int oz = s0 / (Dout * Dout);

    float acc[4][8];
#pragma unroll
    for (int p = 0; p < 4; p++)
#pragma unroll
        for (int c = 0; c < 8; c++) acc[p][c] = 0.f;

    const float* inB = in + (size_t)b * Cin * Din * Din * Din;

    for (int ci0 = 0; ci0 < Cin; ci0 += CI_CHUNK) {
        const int nload = CI_CHUNK * 8 * 64;
        for (int i = tid; i < nload; i += 128) {
            int ci = i / (8 * 64);
            int rem = i % (8 * 64);
            int co = rem / 64;
            int tap = rem % 64;
            ws[ci][co][tap] = w[((size_t)(coBase + co) * Cin + (ci0 + ci)) * 64 + tap];
        }
        __syncthreads();

#pragma unroll 1
        for (int ci = 0; ci < CI_CHUNK; ci++) {
            const float* inC = inB + (size_t)(ci0 + ci) * Din * Din * Din;
#pragma unroll
            for (int kd = 0; kd < 4; kd++) {
                const int iz = 2 * oz + kd - 1;
                if ((unsigned)iz >= (unsigned)Din) continue;
#pragma unroll
                for (int kh = 0; kh < 4; kh++) {
                    const int iy = 2 * oy + kh - 1;
                    if ((unsigned)iy >= (unsigned)Din) continue;
                    const float* row = inC + (size_t)iz * Din * Din + (size_t)iy * Din;
#pragma unroll
                    for (int kw = 0; kw < 4; kw++) {
                        const int ixb = 2 * ox0 + kw - 1;
                        float v[4];
#pragma unroll
                        for (int p = 0; p < 4; p++) {
                            int ix = ixb + 2 * p;
                            v[p] = ((unsigned)ix < (unsigned)Din) ? row[ix] : 0.f;
                        }
                        const int tap = kd * 16 + kh * 4 + kw;
#pragma unroll
                        for (int c = 0; c < 8; c++) {
                            float wv = ws[ci][c][tap];
#pragma unroll
                            for (int p = 0; p < 4; p++) acc[p][c] += v[p] * wv;
                        }
                    }
                }
            }
        }
        __syncthreads();
    }

#pragma unroll
    for (int c = 0; c < 8; c++) {
        float bv = bias[coBase + c];
        size_t base = (((size_t)b * Cout + coBase + c) * Dout + oz) * Dout * Dout
                      + (size_t)oy * Dout + ox0;
#pragma unroll
        for (int p = 0; p < 4; p++) out[base + p] = fmaxf(acc[p][c] + bv, 0.f);
    }
}

__global__ void conv1x1(const float* __restrict__ in, const float* __restrict__ w,
                        const float* __restrict__ bias, float* __restrict__ out)
{
    __shared__ float ws[8][256];
    const int tid = threadIdx.x;
    const int coBase = blockIdx.y * 8;
    const int b = blockIdx.z;
    const int s = blockIdx.x * 128 + tid;

    for (int i = tid; i < 8 * 256; i += 128)
        ws[i / 256][i % 256] = w[(size_t)(coBase + i / 256) * 256 + (i % 256)];
    __syncthreads();

    float acc[8];
#pragma unroll
    for (int c = 0; c < 8; c++) acc[c] = 0.f;

    const float* inB = in + (size_t)b * 256 * 512 + s;
    for (int ci = 0; ci < 256; ci++) {
        float v = inB[(size_t)ci * 512];
#pragma unroll
        for (int c = 0; c < 8; c++) acc[c] += v * ws[c][ci];
    }
#pragma unroll
    for (int c = 0; c < 8; c++)
        out[((size_t)b * 256 + coBase + c) * 512 + s] = acc[c] + bias[coBase + c];
}

__global__ void vq_kernel(const float* __restrict__ lat, const float* __restrict__ cb,
                          float* __restrict__ q, float* __restrict__ idx_out)
{
    __shared__ float4 latS[8][64];
    __shared__ float ln[8];
    __shared__ float bd[8][128];
    __shared__ int bk[8][128];
    __shared__ int wink[8];

    const int tid = threadIdx.x;
    const int vb = blockIdx.x * 8;

    for (int i = tid; i < 8 * 64; i += 128) {
        int v = i >> 6, d4 = i & 63;
        latS[v][d4] = ((const float4*)lat)[(size_t)(vb + v) * 64 + d4];
    }
    __syncthreads();

    if (tid < 8) {
        float s = 0.f;
        for (int d4 = 0; d4 < 64; d4++) {
            float4 l = latS[tid][d4];
            s += l.x * l.x + l.y * l.y + l.z * l.z + l.w * l.w;
        }
        ln[tid] = s;
    }
    __syncthreads();

    float best[8];
    int bestk[8];
#pragma unroll
    for (int v = 0; v < 8; v++) { best[v] = FLT_MAX; bestk[v] = 0; }

    for (int j = 0; j < 8; j++) {
        const int k = tid + j * 128;
        const float4* cbr = (const float4*)(cb + (size_t)k * 256);
        float dot[8];
        float cn = 0.f;
#pragma unroll
        for (int v = 0; v < 8; v++) dot[v] = 0.f;
        for (int d4 = 0; d4 < 64; d4++) {
            float4 c = cbr[d4];
            cn += c.x * c.x + c.y * c.y + c.z * c.z + c.w * c.w;
#pragma unroll
            for (int v = 0; v < 8; v++) {
                float4 l = latS[v][d4];
                dot[v] += c.x * l.x + c.y * l.y + c.z * l.z + c.w * l.w;
            }
        }
#pragma unroll
        for (int v = 0; v < 8; v++) {
            float d2 = ln[v] - 2.f * dot[v] + cn;
            if (d2 < best[v]) { best[v] = d2; bestk[v] = k; }
        }
    }

#pragma unroll
    for (int v = 0; v < 8; v++) { bd[v][tid] = best[v]; bk[v][tid] = bestk[v]; }
    __syncthreads();
    for (int s = 64; s > 0; s >>= 1) {
        if (tid < s) {
#pragma unroll
            for (int v = 0; v < 8; v++) {
                float dB = bd[v][tid + s];
                int kB = bk[v][tid + s];
                float dA = bd[v][tid];
                int kA = bk[v][tid];
                if (dB < dA || (dB == dA && kB < kA)) { bd[v][tid] = dB; bk[v][tid] = kB; }
            }
        }
        __syncthreads();
    }
    if (tid < 8) {
        wink[tid] = bk[tid][0];
        if (idx_out) idx_out[vb + tid] = (float)bk[tid][0];
    }
    __syncthreads();

    for (int i = tid; i < 8 * 256; i += 128) {
        int v = i >> 8, c = i & 255;
        int gn = vb + v;
        int b = gn >> 9, n = gn & 511;
        q[((size_t)b * 256 + c) * 512 + n] = cb[(size_t)wink[v] * 256 + c];
    }
}

template <int Cin, int Cout, int Din>
__global__ void convT_relu(const float* __restrict__ in, const float* __restrict__ w,
                           const float* __restrict__ bias, float* __restrict__ out)
{
    constexpr int Dout = 2 * Din;
    constexpr int CI_CHUNK = 16;
    __shared__ float ws[CI_CHUNK][8][8];

    const int tid = threadIdx.x;
    const int coBase = blockIdx.y * 8;
    const int bz = blockIdx.z;
    const int b = bz >> 3;
    const int cls = bz & 7;
    const int rz = (cls >> 2) & 1, ry = (cls >> 1) & 1, rx = cls & 1;

    const int zoff1 = rz ? 1 : -1;
    const int yoff1 = ry ? 1 : -1;
    const int xoff1 = rx ? 1 : -1;

    const int m0 = blockIdx.x * 512 + tid * 4;
    const int mx0 = m0 % Din;
    const int my = (m0 / Din) % Din;
    const int mz = m0 / (Din * Din);

    float acc[4][8];
#pragma unroll
    for (int p = 0; p < 4; p++)
#pragma unroll
        for (int c = 0; c < 8; c++) acc[p][c] = 0.f;

    const float* inB = in + (size_t)b * Cin * Din * Din * Din;

    for (int ci0 = 0; ci0 < Cin; ci0 += CI_CHUNK) {
        for (int i = tid; i < CI_CHUNK * 64; i += 128) {
            int ci = i / 64;
            int rem = i % 64;
            int co = rem / 8;
            int t = rem % 8;
            int tz = (t >> 2) & 1, ty = (t >> 1) & 1, tx = t & 1;
            int tap = kparity(rz, tz) * 16 + kparity(ry, ty) * 4 + kparity(rx, tx);
            ws[ci][co][t] = w[((size_t)(ci0 + ci) * Cout + coBase + co) * 64 + tap];
        }
        __syncthreads();

#pragma unroll 1
        for (int ci = 0; ci < CI_CHUNK; ci++) {
            const float* inC = inB + (size_t)(ci0 + ci) * Din * Din * Din;
#pragma unroll
            for (int tz = 0; tz < 2; tz++) {
                const int iz = mz + (tz ? zoff1 : 0);
                if ((unsigned)iz >= (unsigned)Din) continue;
#pragma unroll
                for (int ty = 0; ty < 2; ty++) {
                    const int iy = my + (ty ? yoff1 : 0);
                    if ((unsigned)iy >= (unsigned)Din) continue;
                    const float* row = inC + (size_t)iz * Din * Din + (size_t)iy * Din;
#pragma unroll
                    for (int tx = 0; tx < 2; tx++) {
                        const int xo = tx ? xoff1 : 0;
                        float v[4];
#pragma unroll
                        for (int p = 0; p < 4; p++) {
                            int ix = mx0 + p + xo;
                            v[p] = ((unsigned)ix < (unsigned)Din) ? row[ix] : 0.f;
                        }
                        const int t = tz * 4 + ty * 2 + tx;
#pragma unroll
                        for (int c = 0; c < 8; c++) {
                            float wv = ws[ci][c][t];
#pragma unroll
                            for (int p = 0; p < 4; p++) acc[p][c] += v[p] * wv;
                        }
                    }
                }
            }
        }
        __syncthreads();
    }

    const int oz = 2 * mz + rz;
    const int oy = 2 * my + ry;
#pragma unroll
    for (int c = 0; c < 8; c++) {
        float bv = bias[coBase + c];
        size_t base = (((size_t)b * Cout + coBase + c) * Dout + oz) * Dout * Dout
                      + (size_t)oy * Dout;
#pragma unroll
        for (int p = 0; p < 4; p++) {
            int ox = 2 * (mx0 + p) + rx;
            out[base + ox] = fmaxf(acc[p][c] + bv, 0.f);
        }
    }
}

__global__ void conv_final_tanh(const float* __restrict__ in, const float* __restrict__ w,
                                const float* __restrict__ bias, float* __restrict__ out)
{
    __shared__ float ws[3 * 64 * 64];
    const int tid = threadIdx.x;
    for (int i = tid; i < 3 * 64 * 64; i += 128) ws[i] = w[i];
    __syncthreads();

    const int b = blockIdx.z;
    const int z = blockIdx.y;
    const int ry = tid / 16;
    const int quad = tid % 16;
    const int y = blockIdx.x * 8 + ry;
    const int x0 = quad * 4;
    if (y >= 61) return;

    float acc[3][4];
#pragma unroll
    for (int c = 0; c < 3; c++)
#pragma unroll
        for (int p = 0; p < 4; p++) acc[c][p] = 0.f;

    const float* inB = in + (size_t)b * 64 * 64 * 64 * 64;
#pragma unroll 1
    for (int ci = 0; ci < 64; ci++) {
        const float* inC = inB + (size_t)ci * 262144;
#pragma unroll
        for (int kd = 0; kd < 4; kd++) {
            const float* pz = inC + (size_t)(z + kd) * 4096;
#pragma unroll
            for (int kh = 0; kh < 4; kh++) {
                const float* row = pz + (size_t)(y + kh) * 64;
                float v[7];
#pragma unroll
                for (int j = 0; j < 7; j++) {
                    int ix = x0 + j;
                    v[j] = (ix < 64) ? row[ix] : 0.f;
                }
#pragma unroll
                for (int kw = 0; kw < 4; kw++) {
#pragma unroll
                    for (int c = 0; c < 3; c++) {
                        float wv = ws[((size_t)c * 64 + ci) * 64 + kd * 16 + kh * 4 + kw];
#pragma unroll
                        for (int p = 0; p < 4; p++) acc[c][p] += v[kw + p] * wv;
                    }
                }
            }
        }
    }

#pragma unroll
    for (int c = 0; c < 3; c++) {
        float bv = bias[c];
        size_t base = (((size_t)b * 3 + c) * 61 + z) * 61 * 61 + (size_t)y * 61;
#pragma unroll
        for (int p = 0; p < 4; p++) {
            int x = x0 + p;
            if (x < 61) out[base + x] = tanhf(acc[c][p] + bv);
        }
    }
}

// ---------------------------------------------------------------------------

extern "C" void kernel_launch(void* const* d_in, const int* in_sizes, int n_in,
                              void* d_out, int out_size)
{
    const float* x   = (const float*)d_in[0];
    const float* ew1 = (const float*)d_in[1];  const float* eb1 = (const float*)d_in[2];
    const float* ew2 = (const float*)d_in[3];  const float* eb2 = (const float*)d_in[4];
    const float* ew3 = (const float*)d_in[5];  const float* eb3 = (const float*)d_in[6];
    const float* ew4 = (const float*)d_in[7];  const float* eb4 = (const float*)d_in[8];
    const float* cb  = (const float*)d_in[9];
    const float* dw1 = (const float*)d_in[10]; const float* db1 = (const float*)d_in[11];
    const float* dw2 = (const float*)d_in[12]; const float* db2 = (const float*)d_in[13];
    const float* dw3 = (const float*)d_in[14]; const float* db3 = (const float*)d_in[15];
    const float* dw4 = (const float*)d_in[16]; const float* db4 = (const float*)d_in[17];

    float* out = (float*)d_out;
    const int RECON = 2 * 3 * 61 * 61 * 61;
    float* idx_out = (out_size >= RECON + 1024) ? (out + RECON) : nullptr;

    float *h1, *h2, *h3, *lat, *q, *d1, *d2, *d3;
    cudaGetSymbolAddress((void**)&h1, g_h1);
    cudaGetSymbolAddress((void**)&h2, g_h2);
    cudaGetSymbolAddress((void**)&h3, g_h3);
    cudaGetSymbolAddress((void**)&lat, g_lat);
    cudaGetSymbolAddress((void**)&q, g_q);
    cudaGetSymbolAddress((void**)&d1, g_d1);
    cudaGetSymbolAddress((void**)&d2, g_d2);
    cudaGetSymbolAddress((void**)&d3, g_d3);

    // encoder (scalar)
    conv_s2_relu<3, 64, 32><<<dim3(64, 8, 2), 128>>>(x, ew1, eb1, h1);
    conv_s2_relu<64, 128, 16><<<dim3(8, 16, 2), 128>>>(h1, ew2, eb2, h2);
    conv_s2_relu<128, 256, 8><<<dim3(1, 32, 2), 128>>>(h2, ew3, eb3, h3);
    conv1x1<<<dim3(4, 32, 2), 128>>>(h3, ew4, eb4, lat);

    // vector quantization
    vq_kernel<<<128, 128>>>(lat, cb, q, idx_out);

    // decoder: dec1 scalar, dec2/dec3 tensor-core, dec4 scalar
    convT_relu<256, 256, 8><<<dim3(1, 32, 16), 128>>>(q, dw1, db1, d1);
    convT_mma<256, 128, 16><<<dim3(32, 2, 16), 256>>>(d1, dw2, db2, d2);
    convT_mma<128, 64, 32><<<dim3(256, 1, 16), 256>>>(d2, dw3, db3, d3);
    conv_final_tanh<<<dim3(8, 61, 2), 128>>>(d3, dw4, db4, out);
}

// round 7
// speedup vs baseline: 2.1118x; 1.1361x over previous
#include <cuda_runtime.h>
#include <cuda_fp16.h>
#include <math.h>
#include <cfloat>

// ---------------------------------------------------------------------------
// VQGAN forward. dec1/dec2/dec3 via mma.sync fp16 (2-term input split, fp32
// accumulate), K ordered (tap, ci-pair) -> all fragments aligned LDS.32.
// Tile spans ZT z-planes x R y-rows (M = ZT*R*Din = 128).
// Encoder + dec4: scalar round-1 kernels.
// ---------------------------------------------------------------------------

#define NB 2

__device__ float g_h1[(size_t)NB * 64 * 32 * 32 * 32];
__device__ float g_h2[(size_t)NB * 128 * 16 * 16 * 16];
__device__ float g_h3[(size_t)NB * 256 * 8 * 8 * 8];
__device__ float g_lat[(size_t)NB * 256 * 512];
__device__ float g_q[(size_t)NB * 256 * 512];
__device__ float g_d1[(size_t)NB * 256 * 16 * 16 * 16];
__device__ float g_d2[(size_t)NB * 128 * 32 * 32 * 32];
__device__ float g_d3[(size_t)NB * 64 * 64 * 64 * 64];

// ---- helpers ---------------------------------------------------------------
__device__ __forceinline__ unsigned pack_h2(float a, float b) {
    __half2 t = __floats2half2_rn(a, b);   // low = a, high = b
    return *reinterpret_cast<unsigned*>(&t);
}
__device__ __forceinline__ void mma16816(float* c, const unsigned* a, const unsigned* b) {
    asm volatile("mma.sync.aligned.m16n8k16.row.col.f32.f16.f16.f32 "
                 "{%0,%1,%2,%3},{%4,%5,%6,%7},{%8,%9},{%0,%1,%2,%3};"
                 : "+f"(c[0]), "+f"(c[1]), "+f"(c[2]), "+f"(c[3])
                 : "r"(a[0]), "r"(a[1]), "r"(a[2]), "r"(a[3]),
                   "r"(b[0]), "r"(b[1]));
}
__device__ __forceinline__ int kparity(int r, int t) { return r ? (2 - 2 * t) : (1 + 2 * t); }

// ---------------------------------------------------------------------------
// convT k4 s2 p1 + ReLU via tensor cores (fp16 2-term).
// GEMM per (batch, parity class): M = Din^3, N = Cout, K = 8 taps x Cin.
// k16 block = 8 taps x 2 ci. Input tile staged as h2 words {v_ci0, v_ci1}
// (hi + residual lo); weights single fp16 as {w_ci0, w_ci1} per (co, tap).
// M-tile = ZT z-planes x R y-rows x Din x-cols = 128. Halo: ZT+1 z-planes.
// CTA: M=128 x N=64, 8 warps (4Mx2N), double-buffered.
// ---------------------------------------------------------------------------
template <int Cin, int Cout, int Din, int ZT, int R>
__global__ void __launch_bounds__(256)
convT_mma(const float* __restrict__ in, const float* __restrict__ w,
          const float* __restrict__ bias, float* __restrict__ out)
{
    constexpr int Dout = 2 * Din;
    constexpr int XS = Din + 2;
    constexpr int YS = R + 2;
    constexpr int ZS = YS * XS;             // words per z plane
    constexpr int PLANES = ZT + 1;
    constexpr int TW = PLANES * ZS;         // tile words
    constexpr int NIT = Cin / 2;
    constexpr int LDW = (TW + 255) / 256;
    constexpr int BP = 9;                   // padded B pitch
    constexpr int TPY = Din / R;            // y-tiles per z-group
    constexpr size_t D3 = (size_t)Din * Din * Din;

    __shared__ unsigned rawHi[2][TW];
    __shared__ unsigned rawLo[2][TW];
    __shared__ unsigned Bh_s[2][64 * BP];

    const int tid = threadIdx.x, lane = tid & 31, wid = tid >> 5;
    const int wm = wid & 3, wn = wid >> 2;
    const int bzz = blockIdx.z, bb = bzz >> 3, cls = bzz & 7;
    const int rz = (cls >> 2) & 1, ry = (cls >> 1) & 1, rx = cls & 1;
    const int zoff1 = rz ? 1 : -1, yoff1 = ry ? 1 : -1, xoff1 = rx ? 1 : -1;
    const int mz0 = (blockIdx.x / TPY) * ZT;
    const int my0 = (blockIdx.x % TPY) * R;
    const int coBase = blockIdx.y * 64;
    const int zlo = 1 - rz;                 // plane index offset: gz = mz0 + p - zlo

    // ---- input-tile staging descriptors (per 32-bit word) ----
    size_t rs_goff[LDW];
    int rs_i[LDW];
    bool rs_ok[LDW], rs_act[LDW];
#pragma unroll
    for (int l = 0; l < LDW; l++) {
        int i = tid + l * 256;
        bool act = (i < TW);
        int ii = act ? i : 0;
        int p = ii / ZS;
        int r2 = ii % ZS;
        int yy = r2 / XS, xx = r2 % XS;
        int gz = mz0 + p - zlo;
        int gy = my0 + yy - 1;
        int gx = xx - 1;
        bool ok = act && (unsigned)gz < (unsigned)Din &&
                  (unsigned)gy < (unsigned)Din && (unsigned)gx < (unsigned)Din;
        rs_goff[l] = ok ? (((size_t)bb * Cin * Din + (size_t)gz) * (Din * Din)
                           + (size_t)gy * Din + gx)
                        : 0;
        rs_i[l] = ii;
        rs_ok[l] = ok;
        rs_act[l] = act;
    }

    // ---- weight staging descriptors: slot = (co, tap) ----
    size_t ws_g[2];
    int ws_i[2];
#pragma unroll
    for (int l = 0; l < 2; l++) {
        int q = tid + l * 256;          // 0..511
        int co = q >> 3, t = q & 7;
        int tz = (t >> 2) & 1, ty = (t >> 1) & 1, tx = t & 1;
        int kd = kparity(rz, tz), kh = kparity(ry, ty), kw = kparity(rx, tx);
        ws_g[l] = (size_t)(coBase + co) * 64 + kd * 16 + kh * 4 + kw;   // ci = 0
        ws_i[l] = co * BP + t;
    }

    // ---- A fragment word offsets: [mtile][rowhalf][khalf] ----
    const int kp = lane & 3;
    int aoff[2][2][2];
#pragma unroll
    for (int t = 0; t < 2; t++)
#pragma unroll
        for (int h = 0; h < 2; h++)
#pragma unroll
            for (int q = 0; q < 2; q++) {
                int tap = kp + 4 * q;
                int tzk = (tap >> 2) & 1, tyk = (tap >> 1) & 1, txk = tap & 1;
                int mloc = wm * 32 + t * 16 + (lane >> 2) + h * 8;
                int mzl = mloc / (R * Din);
                int rem = mloc % (R * Din);
                int myl = rem / Din, mx = rem % Din;
                int plane = mzl + (tzk ? zoff1 : 0) + zlo;
                int yy = myl + (tyk ? yoff1 : 0) + 1;
                int xx = mx + (txk ? xoff1 : 0) + 1;
                aoff[t][h][q] = plane * ZS + yy * XS + xx;
            }

    int boff[4];
#pragma unroll
    for (int j = 0; j < 4; j++)
        boff[j] = (wn * 32 + j * 8 + (lane >> 2)) * BP + kp;

    float C[2][4][4];
#pragma unroll
    for (int t = 0; t < 2; t++)
#pragma unroll
        for (int j = 0; j < 4; j++)
#pragma unroll
            for (int k = 0; k < 4; k++) C[t][j][k] = 0.f;

    // ---- pipelined main loop (2 ci per iter) ----
    float rv0[LDW], rv1[LDW], wa[2], wc[2];

#define STAGE_REGS(IT)                                                          \
    {                                                                           \
        size_t cioff = (size_t)(2 * (IT)) * D3;                                 \
        _Pragma("unroll")                                                       \
        for (int l = 0; l < LDW; l++) {                                         \
            rv0[l] = rs_ok[l] ? __ldg(in + rs_goff[l] + cioff) : 0.f;           \
            rv1[l] = rs_ok[l] ? __ldg(in + rs_goff[l] + cioff + D3) : 0.f;      \
        }                                                                       \
        size_t woff = (size_t)(2 * (IT)) * Cout * 64;                           \
        _Pragma("unroll")                                                       \
        for (int l = 0; l < 2; l++) {                                           \
            wa[l] = __ldg(w + ws_g[l] + woff);                                  \
            wc[l] = __ldg(w + ws_g[l] + woff + (size_t)Cout * 64);              \
        }                                                                       \
    }

#define STAGE_STORE(BF)                                                         \
    {                                                                           \
        _Pragma("unroll")                                                       \
        for (int l = 0; l < LDW; l++)                                           \
            if (rs_act[l]) {                                                    \
                float v0 = rv0[l], v1 = rv1[l];                                 \
                float h0 = __half2float(__float2half_rn(v0));                   \
                float h1 = __half2float(__float2half_rn(v1));                   \
                rawHi[BF][rs_i[l]] = pack_h2(v0, v1);                           \
                rawLo[BF][rs_i[l]] = pack_h2(v0 - h0, v1 - h1);                 \
            }                                                                   \
        _Pragma("unroll")                                                       \
        for (int l = 0; l < 2; l++)                                             \
            Bh_s[BF][ws_i[l]] = pack_h2(wa[l], wc[l]);                          \
    }

#define COMPUTE(BF)                                                             \
    {                                                                           \
        unsigned Ah[2][4], Al[2][4];                                            \
        _Pragma("unroll")                                                       \
        for (int t = 0; t < 2; t++) {                                           \
            Ah[t][0] = rawHi[BF][aoff[t][0][0]];                                \
            Ah[t][1] = rawHi[BF][aoff[t][1][0]];                                \
            Ah[t][2] = rawHi[BF][aoff[t][0][1]];                                \
            Ah[t][3] = rawHi[BF][aoff[t][1][1]];                                \
            Al[t][0] = rawLo[BF][aoff[t][0][0]];                                \
            Al[t][1] = rawLo[BF][aoff[t][1][0]];                                \
            Al[t][2] = rawLo[BF][aoff[t][0][1]];                                \
            Al[t][3] = rawLo[BF][aoff[t][1][1]];                                \
        }                                                                       \
        unsigned Bh[4][2];                                                      \
        _Pragma("unroll")                                                       \
        for (int j = 0; j < 4; j++) {                                           \
            Bh[j][0] = Bh_s[BF][boff[j]];                                       \
            Bh[j][1] = Bh_s[BF][boff[j] + 4];                                   \
        }                                                                       \
        _Pragma("unroll")                                                       \
        for (int t = 0; t < 2; t++)                                             \
            _Pragma("unroll")                                                   \
            for (int j = 0; j < 4; j++) {                                       \
                mma16816(C[t][j], Ah[t], Bh[j]);                                \
                mma16816(C[t][j], Al[t], Bh[j]);                                \
            }                                                                   \
    }

    STAGE_REGS(0);
    STAGE_STORE(0);
    __syncthreads();

    int bf = 0;
    for (int it = 0; it < NIT; ++it) {
        bool more = (it + 1 < NIT);
        if (more) STAGE_REGS(it + 1);
        COMPUTE(bf);
        if (more) {
            STAGE_STORE(bf ^ 1);
            bf ^= 1;
            __syncthreads();
        }
    }

#undef STAGE_REGS
#undef STAGE_STORE
#undef COMPUTE

    // ---- epilogue: bias + ReLU + scattered store ----
#pragma unroll
    for (int j = 0; j < 4; j++) {
        int n0 = coBase + wn * 32 + j * 8 + (lane & 3) * 2;
        float bv0 = bias[n0], bv1 = bias[n0 + 1];
#pragma unroll
        for (int t = 0; t < 2; t++)
#pragma unroll
            for (int h = 0; h < 2; h++) {
                int mloc = wm * 32 + t * 16 + (lane >> 2) + h * 8;
                int mzl = mloc / (R * Din);
                int rem = mloc % (R * Din);
                int myl = rem / Din, mx = rem % Din;
                int oz = 2 * (mz0 + mzl) + rz;
                int oy = 2 * (my0 + myl) + ry;
                int ox = 2 * mx + rx;
                size_t a = (((size_t)bb * Cout + n0) * Dout + oz) * ((size_t)Dout * Dout)
                           + (size_t)oy * Dout + ox;
                out[a] = fmaxf(C[t][j][2 * h] + bv0, 0.f);
                out[a + (size_t)Dout * Dout * Dout] = fmaxf(C[t][j][2 * h + 1] + bv1, 0.f);
            }
    }
}

// ---------------------------------------------------------------------------
// Round-1 scalar kernels for everything else.
// ---------------------------------------------------------------------------
template <int Cin, int Cout, int Dout>
__global__ void conv_s2_relu(const float* __restrict__ in,
                             const float* __restrict__ w,
                             const float* __restrict__ bias,
                             float* __restrict__ out)
{
    constexpr int Din = 2 * Dout;
    constexpr int CI_CHUNK = (Cin < 16) ? Cin : 16;
    __shared__ float ws[CI_CHUNK][8][64];

    const int tid = threadIdx.x;
    const int coBase = blockIdx.y * 8;
    const int b = blockIdx.z;
    const int s0 = blockIdx.x * 512 + tid * 4;
    const int ox0 = s0 % Dout;
    const int oy = (s0 / Dout) % Dout;
    const int oz = s0 / (Dout * Dout);

    float acc[4][8];
#pragma unroll
    for (int p = 0; p < 4; p++)
#pragma unroll
        for (int c = 0; c < 8; c++) acc[p][c] = 0.f;

    const float* inB = in + (size_t)b * Cin * Din * Din * Din;

    for (int ci0 = 0; ci0 < Cin; ci0 += CI_CHUNK) {
        const int nload = CI_CHUNK * 8 * 64;
        for (int i = tid; i < nload; i += 128) {
            int ci = i / (8 * 64);
            int rem = i % (8 * 64);
            int co = rem / 64;
            int tap = rem % 64;
            ws[ci][co][tap] = w[((size_t)(coBase + co) * Cin + (ci0 + ci)) * 64 + tap];
        }
        __syncthreads();

#pragma unroll 1
        for (int ci = 0; ci < CI_CHUNK; ci++) {
            const float* inC = inB + (size_t)(ci0 + ci) * Din * Din * Din;
#pragma unroll
            for (int kd = 0; kd < 4; kd++) {
                const int iz = 2 * oz + kd - 1;
                if ((unsigned)iz >= (unsigned)Din) continue;
#pragma unroll
                for (int kh = 0; kh < 4; kh++) {
                    const int iy = 2 * oy + kh - 1;
                    if ((unsigned)iy >= (unsigned)Din) continue;
                    const float* row = inC + (size_t)iz * Din * Din + (size_t)iy * Din;
#pragma unroll
                    for (int kw = 0; kw < 4; kw++) {
                        const int ixb = 2 * ox0 + kw - 1;
                        float v[4];
#pragma unroll
                        for (int p = 0; p < 4; p++) {
                            int ix = ixb + 2 * p;
                            v[p] = ((unsigned)ix < (unsigned)Din) ? row[ix] : 0.f;
                        }
                        const int tap = kd * 16 + kh * 4 + kw;
#pragma unroll
                        for (int c = 0; c < 8; c++) {
                            float wv = ws[ci][c][tap];
#pragma unroll
                            for (int p = 0; p < 4; p++) acc[p][c] += v[p] * wv;
                        }
                    }
                }
            }
        }
        __syncthreads();
    }

#pragma unroll
    for (int c = 0; c < 8; c++) {
        float bv = bias[coBase + c];
        size_t base = (((size_t)b * Cout + coBase + c) * Dout + oz) * Dout * Dout
                      + (size_t)oy * Dout + ox0;
#pragma unroll
        for (int p = 0; p < 4; p++) out[base + p] = fmaxf(acc[p][c] + bv, 0.f);
    }
}

__global__ void conv1x1(const float* __restrict__ in, const float* __restrict__ w,
                        const float* __restrict__ bias, float* __restrict__ out)
{
    __shared__ float ws[8][256];
    const int tid = threadIdx.x;
    const int coBase = blockIdx.y * 8;
    const int b = blockIdx.z;
    const int s = blockIdx.x * 128 + tid;

    for (int i = tid; i < 8 * 256; i += 128)
        ws[i / 256][i % 256] = w[(size_t)(coBase + i / 256) * 256 + (i % 256)];
    __syncthreads();

    float acc[8];
#pragma unroll
    for (int c = 0; c < 8; c++) acc[c] = 0.f;

    const float* inB = in + (size_t)b * 256 * 512 + s;
    for (int ci = 0; ci < 256; ci++) {
        float v = inB[(size_t)ci * 512];
#pragma unroll
        for (int c = 0; c < 8; c++) acc[c] += v * ws[c][ci];
    }
#pragma unroll
    for (int c = 0; c < 8; c++)
        out[((size_t)b * 256 + coBase + c) * 512 + s] = acc[c] + bias[coBase + c];
}

__global__ void vq_kernel(const float* __restrict__ lat, const float* __restrict__ cb,
                          float* __restrict__ q, float* __restrict__ idx_out)
{
    __shared__ float4 latS[8][64];
    __shared__ float ln[8];
    __shared__ float bd[8][128];
    __shared__ int bk[8][128];
    __shared__ int wink[8];

    const int tid = threadIdx.x;
    const int vb = blockIdx.x * 8;

    for (int i = tid; i < 8 * 64; i += 128) {
        int v = i >> 6, d4 = i & 63;
        latS[v][d4] = ((const float4*)lat)[(size_t)(vb + v) * 64 + d4];
    }
    __syncthreads();

    if (tid < 8) {
        float s = 0.f;
        for (int d4 = 0; d4 < 64; d4++) {
            float4 l = latS[tid][d4];
            s += l.x * l.x + l.y * l.y + l.z * l.z + l.w * l.w;
        }
        ln[tid] = s;
    }
    __syncthreads();

    float best[8];
    int bestk[8];
#pragma unroll
    for (int v = 0; v < 8; v++) { best[v] = FLT_MAX; bestk[v] = 0; }

    for (int j = 0; j < 8; j++) {
        const int k = tid + j * 128;
        const float4* cbr = (const float4*)(cb + (size_t)k * 256);
        float dot[8];
        float cn = 0.f;
#pragma unroll
        for (int v = 0; v < 8; v++) dot[v] = 0.f;
        for (int d4 = 0; d4 < 64; d4++) {
            float4 c = cbr[d4];
            cn += c.x * c.x + c.y * c.y + c.z * c.z + c.w * c.w;
#pragma unroll
            for (int v = 0; v < 8; v++) {
                float4 l = latS[v][d4];
                dot[v] += c.x * l.x + c.y * l.y + c.z * l.z + c.w * l.w;
            }
        }
#pragma unroll
        for (int v = 0; v < 8; v++) {
            float d2 = ln[v] - 2.f * dot[v] + cn;
            if (d2 < best[v]) { best[v] = d2; bestk[v] = k; }
        }
    }

#pragma unroll
    for (int v = 0; v < 8; v++) { bd[v][tid] = best[v]; bk[v][tid] = bestk[v]; }
    __syncthreads();
    for (int s = 64; s > 0; s >>= 1) {
        if (tid < s) {
#pragma unroll
            for (int v = 0; v < 8; v++) {
                float dB = bd[v][tid + s];
                int kB = bk[v][tid + s];
                float dA = bd[v][tid];
                int kA = bk[v][tid];
                if (dB < dA || (dB == dA && kB < kA)) { bd[v][tid] = dB; bk[v][tid] = kB; }
            }
        }
        __syncthreads();
    }
    if (tid < 8) {
        wink[tid] = bk[tid][0];
        if (idx_out) idx_out[vb + tid] = (float)bk[tid][0];
    }
    __syncthreads();

    for (int i = tid; i < 8 * 256; i += 128) {
        int v = i >> 8, c = i & 255;
        int gn = vb + v;
        int b = gn >> 9, n = gn & 511;
        q[((size_t)b * 256 + c) * 512 + n] = cb[(size_t)wink[v] * 256 + c];
    }
}

__global__ void conv_final_tanh(const float* __restrict__ in, const float* __restrict__ w,
                                const float* __restrict__ bias, float* __restrict__ out)
{
    __shared__ float ws[3 * 64 * 64];
    const int tid = threadIdx.x;
    for (int i = tid; i < 3 * 64 * 64; i += 128) ws[i] = w[i];
    __syncthreads();

    const int b = blockIdx.z;
    const int z = blockIdx.y;
    const int ry = tid / 16;
    const int quad = tid % 16;
    const int y = blockIdx.x * 8 + ry;
    const int x0 = quad * 4;
    if (y >= 61) return;

    float acc[3][4];
#pragma unroll
    for (int c = 0; c < 3; c++)
#pragma unroll
        for (int p = 0; p < 4; p++) acc[c][p] = 0.f;

    const float* inB = in + (size_t)b * 64 * 64 * 64 * 64;
#pragma unroll 1
    for (int ci = 0; ci < 64; ci++) {
        const float* inC = inB + (size_t)ci * 262144;
#pragma unroll
        for (int kd = 0; kd < 4; kd++) {
            const float* pz = inC + (size_t)(z + kd) * 4096;
#pragma unroll
            for (int kh = 0; kh < 4; kh++) {
                const float* row = pz + (size_t)(y + kh) * 64;
                float v[7];
#pragma unroll
                for (int j = 0; j < 7; j++) {
                    int ix = x0 + j;
                    v[j] = (ix < 64) ? row[ix] : 0.f;
                }
#pragma unroll
                for (int kw = 0; kw < 4; kw++) {
#pragma unroll
                    for (int c = 0; c < 3; c++) {
                        float wv = ws[((size_t)c * 64 + ci) * 64 + kd * 16 + kh * 4 + kw];
#pragma unroll
                        for (int p = 0; p < 4; p++) acc[c][p] += v[kw + p] * wv;
                    }
                }
            }
        }
    }

#pragma unroll
    for (int c = 0; c < 3; c++) {
        float bv = bias[c];
        size_t base = (((size_t)b * 3 + c) * 61 + z) * 61 * 61 + (size_t)y * 61;
#pragma unroll
        for (int p = 0; p < 4; p++) {
            int x = x0 + p;
            if (x < 61) out[base + x] = tanhf(acc[c][p] + bv);
        }
    }
}

// ---------------------------------------------------------------------------

extern "C" void kernel_launch(void* const* d_in, const int* in_sizes, int n_in,
                              void* d_out, int out_size)
{
    const float* x   = (const float*)d_in[0];
    const float* ew1 = (const float*)d_in[1];  const float* eb1 = (const float*)d_in[2];
    const float* ew2 = (const float*)d_in[3];  const float* eb2 = (const float*)d_in[4];
    const float* ew3 = (const float*)d_in[5];  const float* eb3 = (const float*)d_in[6];
    const float* ew4 = (const float*)d_in[7];  const float* eb4 = (const float*)d_in[8];
    const float* cb  = (const float*)d_in[9];
    const float* dw1 = (const float*)d_in[10]; const float* db1 = (const float*)d_in[11];
    const float* dw2 = (const float*)d_in[12]; const float* db2 = (const float*)d_in[13];
    const float* dw3 = (const float*)d_in[14]; const float* db3 = (const float*)d_in[15];
    const float* dw4 = (const float*)d_in[16]; const float* db4 = (const float*)d_in[17];

    float* out = (float*)d_out;
    const int RECON = 2 * 3 * 61 * 61 * 61;
    float* idx_out = (out_size >= RECON + 1024) ? (out + RECON) : nullptr;

    float *h1, *h2, *h3, *lat, *q, *d1, *d2, *d3;
    cudaGetSymbolAddress((void**)&h1, g_h1);
    cudaGetSymbolAddress((void**)&h2, g_h2);
    cudaGetSymbolAddress((void**)&h3, g_h3);
    cudaGetSymbolAddress((void**)&lat, g_lat);
    cudaGetSymbolAddress((void**)&q, g_q);
    cudaGetSymbolAddress((void**)&d1, g_d1);
    cudaGetSymbolAddress((void**)&d2, g_d2);
    cudaGetSymbolAddress((void**)&d3, g_d3);

    // encoder (scalar)
    conv_s2_relu<3, 64, 32><<<dim3(64, 8, 2), 128>>>(x, ew1, eb1, h1);
    conv_s2_relu<64, 128, 16><<<dim3(8, 16, 2), 128>>>(h1, ew2, eb2, h2);
    conv_s2_relu<128, 256, 8><<<dim3(1, 32, 2), 128>>>(h2, ew3, eb3, h3);
    conv1x1<<<dim3(4, 32, 2), 128>>>(h3, ew4, eb4, lat);

    // vector quantization
    vq_kernel<<<128, 128>>>(lat, cb, q, idx_out);

    // decoder: dec1/dec2/dec3 tensor-core, dec4 scalar
    convT_mma<256, 256, 8, 2, 8><<<dim3(4, 4, 16), 256>>>(q, dw1, db1, d1);
    convT_mma<256, 128, 16, 1, 8><<<dim3(32, 2, 16), 256>>>(d1, dw2, db2, d2);
    convT_mma<128, 64, 32, 1, 4><<<dim3(256, 1, 16), 256>>>(d2, dw3, db3, d3);
    conv_final_tanh<<<dim3(8, 61, 2), 128>>>(d3, dw4, db4, out);
}